// round 4
// baseline (speedup 1.0000x reference)
#include <cuda_runtime.h>
#include <cuda_bf16.h>
#include <math.h>
#include <stdint.h>

#define Bn 16384
#define Ln 50
#define Dn 128
#define Fn 6
#define CINn 2688
#define H1N 512
#define H2N 256

// ---------------- scratch (static device globals) ---------------------------
__device__ __align__(16) float g_x  [Bn * Fn * Dn];            // fp32 x (residual)
__device__ __align__(16) __nv_bfloat16 g_x_hi[Bn * Fn * Dn];
__device__ __align__(16) __nv_bfloat16 g_x_lo[Bn * Fn * Dn];
__device__ __align__(16) float g_hp [Bn * Fn * Dn];            // hp[b,n,h*32+o]
__device__ __align__(16) __nv_bfloat16 g_s_hi[Bn * Fn * Dn];
__device__ __align__(16) __nv_bfloat16 g_s_lo[Bn * Fn * Dn];
__device__ __align__(16) float g_vid[Bn * 5 * Dn];
__device__ __align__(16) __nv_bfloat16 g_c_hi[Bn * CINn];
__device__ __align__(16) __nv_bfloat16 g_c_lo[Bn * CINn];
__device__ __align__(16) __nv_bfloat16 g_h1_hi[Bn * H1N];
__device__ __align__(16) __nv_bfloat16 g_h1_lo[Bn * H1N];
__device__ __align__(16) float g_h2 [Bn * H2N];
__device__ __align__(16) __nv_bfloat16 g_w1t_hi[H1N * CINn];
__device__ __align__(16) __nv_bfloat16 g_w1t_lo[H1N * CINn];
__device__ __align__(16) __nv_bfloat16 g_w2t_hi[H2N * H1N];
__device__ __align__(16) __nv_bfloat16 g_w2t_lo[H2N * H1N];
__device__ __align__(16) __nv_bfloat16 g_wg_hi[Dn * Dn];       // gnn_W as [n=h*32+o][k=i]
__device__ __align__(16) __nv_bfloat16 g_wg_lo[Dn * Dn];
__device__ __align__(16) __nv_bfloat16 g_wb_hi[5 * Dn * Dn];   // bi_W as [f][e][d]
__device__ __align__(16) __nv_bfloat16 g_wb_lo[5 * Dn * Dn];

// ---------------- PTX helpers (sm_80-level only) -----------------------------
__device__ __forceinline__ uint32_t smem_u32(const void* p) {
    uint32_t a;
    asm("{ .reg .u64 t; cvta.to.shared.u64 t, %1; cvt.u32.u64 %0, t; }" : "=r"(a) : "l"(p));
    return a;
}
__device__ __forceinline__ void cp16(uint32_t dst, const void* src) {
    asm volatile("cp.async.cg.shared.global [%0], [%1], 16;" :: "r"(dst), "l"(src));
}
__device__ __forceinline__ void cp_commit() {
    asm volatile("cp.async.commit_group;" ::: "memory");
}
template <int N>
__device__ __forceinline__ void cp_wait() {
    asm volatile("cp.async.wait_group %0;" :: "n"(N) : "memory");
}
__device__ __forceinline__ void ldsm4(uint32_t* r, uint32_t addr) {
    asm volatile("ldmatrix.sync.aligned.m8n8.x4.shared.b16 {%0,%1,%2,%3}, [%4];"
                 : "=r"(r[0]), "=r"(r[1]), "=r"(r[2]), "=r"(r[3]) : "r"(addr));
}
__device__ __forceinline__ void mma_bf16(float* d, const uint32_t* a, const uint32_t* b) {
    asm volatile(
        "mma.sync.aligned.m16n8k16.row.col.f32.bf16.bf16.f32 "
        "{%0,%1,%2,%3}, {%4,%5,%6,%7}, {%8,%9}, {%0,%1,%2,%3};"
        : "+f"(d[0]), "+f"(d[1]), "+f"(d[2]), "+f"(d[3])
        : "r"(a[0]), "r"(a[1]), "r"(a[2]), "r"(a[3]), "r"(b[0]), "r"(b[1]));
}
__device__ __forceinline__ void split_bf16(float v, __nv_bfloat16& hi, __nv_bfloat16& lo) {
    hi = __float2bfloat16(v);
    lo = __float2bfloat16(v - __bfloat162float(hi));
}

// ---------------- K1: features -> x (fp32 + bf16 hi/lo) ---------------------
__global__ __launch_bounds__(128) void k_features(
    const int* __restrict__ item_id, const float* __restrict__ item_mm,
    const int* __restrict__ likes, const int* __restrict__ views,
    const int* __restrict__ item_seq, const float* __restrict__ item_emb,
    const float* __restrict__ cate_emb, const float* __restrict__ mm_w,
    const float* __restrict__ mm_b, const float* __restrict__ ln_g,
    const float* __restrict__ ln_b)
{
    int b = blockIdx.x, t = threadIdx.x;
    int lane = t & 31, w = t >> 5;
    __shared__ float sm[Dn];
    __shared__ float red[8];

    sm[t] = item_mm[b * Dn + t];
    __syncthreads();

    float y = mm_b[t];
    #pragma unroll 16
    for (int i = 0; i < Dn; i++) y = fmaf(sm[i], mm_w[i * Dn + t], y);

    float s1 = y, s2 = y * y;
    #pragma unroll
    for (int o = 16; o; o >>= 1) {
        s1 += __shfl_xor_sync(0xffffffffu, s1, o);
        s2 += __shfl_xor_sync(0xffffffffu, s2, o);
    }
    if (!lane) { red[w] = s1; red[4 + w] = s2; }
    __syncthreads();
    float mu = (red[0] + red[1] + red[2] + red[3]) * (1.f / Dn);
    float m2 = (red[4] + red[5] + red[6] + red[7]) * (1.f / Dn);
    float var = m2 - mu * mu;
    float yn = (y - mu) * rsqrtf(var + 1e-5f) * ln_g[t] + ln_b[t];
    float img = 0.5f * yn * (1.f + erff(yn * 0.70710678118654752f));

    float hs = 0.f, cnt = 0.f;
    const int* seq = item_seq + b * Ln;
    for (int l = 0; l < Ln; l++) {
        int id = seq[l];
        if (id != 0) { hs += item_emb[(size_t)id * Dn + t]; cnt += 1.f; }
    }
    float hist = hs / fmaxf(cnt, 1.f);

    float v[Fn];
    v[0] = 0.f;
    v[1] = cate_emb[likes[b] * Dn + t];
    v[2] = cate_emb[views[b] * Dn + t];
    v[3] = item_emb[(size_t)item_id[b] * Dn + t];
    v[4] = img;
    v[5] = hist;

    float* xb = g_x + (size_t)b * (Fn * Dn);
    __nv_bfloat16* xh = g_x_hi + (size_t)b * (Fn * Dn);
    __nv_bfloat16* xl = g_x_lo + (size_t)b * (Fn * Dn);
    #pragma unroll
    for (int n = 0; n < Fn; n++) {
        xb[n * Dn + t] = v[n];
        __nv_bfloat16 hi, lo;
        split_bf16(v[n], hi, lo);
        xh[n * Dn + t] = hi;
        xl[n * Dn + t] = lo;
    }
}

// ---------------- K2: GAT (post-hp) + SE -> c_hi/c_lo[:, :768], s hi/lo ------
__global__ __launch_bounds__(128) void k_gnn(
    const float* __restrict__ gnn_a,
    const float* __restrict__ se_w1, const float* __restrict__ se_b1,
    const float* __restrict__ se_w2, const float* __restrict__ se_b2)
{
    int b = blockIdx.x, t = threadIdx.x;
    int h = t >> 5, lane = t & 31;
    __shared__ float red[4 * Fn];

    const float* hpb = g_hp + (size_t)b * Fn * Dn;
    const float* xb  = g_x  + (size_t)b * Fn * Dn;
    float hp[Fn], xv[Fn];
    #pragma unroll
    for (int n = 0; n < Fn; n++) {
        hp[n] = hpb[n * Dn + t];
        xv[n] = xb[n * Dn + t];
    }

    float a1 = gnn_a[h * 64 + lane];
    float a2 = gnn_a[h * 64 + 32 + lane];
    float ei[Fn], ej[Fn];
    #pragma unroll
    for (int n = 0; n < Fn; n++) {
        float v1 = hp[n] * a1, v2 = hp[n] * a2;
        #pragma unroll
        for (int o = 16; o; o >>= 1) {
            v1 += __shfl_xor_sync(0xffffffffu, v1, o);
            v2 += __shfl_xor_sync(0xffffffffu, v2, o);
        }
        ei[n] = v1; ej[n] = v2;
    }

    float gnn[Fn];
    #pragma unroll
    for (int n = 0; n < Fn; n++) {
        float em[Fn], mx = -1e30f;
        #pragma unroll
        for (int m = 0; m < Fn; m++) {
            float e = ei[n] + ej[m];
            e = e > 0.f ? e : 0.2f * e;
            em[m] = e; mx = fmaxf(mx, e);
        }
        float ss = 0.f;
        #pragma unroll
        for (int m = 0; m < Fn; m++) { em[m] = expf(em[m] - mx); ss += em[m]; }
        float inv = 1.f / ss, acc = 0.f;
        #pragma unroll
        for (int m = 0; m < Fn; m++) acc = fmaf(em[m], hp[m], acc);
        float hn = acc * inv + xv[n];
        gnn[n] = hn > 0.f ? hn : expm1f(hn);
    }

    #pragma unroll
    for (int n = 0; n < Fn; n++) {
        float v = gnn[n];
        #pragma unroll
        for (int o = 16; o; o >>= 1) v += __shfl_xor_sync(0xffffffffu, v, o);
        if (!lane) red[h * Fn + n] = v;
    }
    __syncthreads();

    float wv[Fn];
    {
        float z[Fn];
        #pragma unroll
        for (int n = 0; n < Fn; n++)
            z[n] = (red[0 * Fn + n] + red[1 * Fn + n] + red[2 * Fn + n] + red[3 * Fn + n]) * (1.f / Dn);
        float a[3];
        #pragma unroll
        for (int k = 0; k < 3; k++) {
            float v = se_b1[k];
            #pragma unroll
            for (int n = 0; n < Fn; n++) v = fmaf(z[n], se_w1[n * 3 + k], v);
            a[k] = fmaxf(v, 0.f);
        }
        #pragma unroll
        for (int f = 0; f < Fn; f++) {
            float v = se_b2[f];
            #pragma unroll
            for (int k = 0; k < 3; k++) v = fmaf(a[k], se_w2[k * 6 + f], v);
            wv[f] = 1.f / (1.f + expf(-v));
        }
    }

    __nv_bfloat16* ch = g_c_hi + (size_t)b * CINn;
    __nv_bfloat16* cl = g_c_lo + (size_t)b * CINn;
    __nv_bfloat16* sh = g_s_hi + (size_t)b * Fn * Dn;
    __nv_bfloat16* sl = g_s_lo + (size_t)b * Fn * Dn;
    #pragma unroll
    for (int n = 0; n < Fn; n++) {
        float v = gnn[n];
        __nv_bfloat16 hi, lo;
        split_bf16(v, hi, lo);
        ch[n * Dn + t] = hi;
        cl[n * Dn + t] = lo;
        float sv = v * wv[n];
        split_bf16(sv, hi, lo);
        sh[n * Dn + t] = hi;
        sl[n * Dn + t] = lo;
    }
}

// ---------------- K4: bilinear pairs -> c_hi/c_lo[:, 768:] -------------------
__global__ __launch_bounds__(128) void k_pairs()
{
    int b = blockIdx.x, t = threadIdx.x;
    const float* vid = g_vid + (size_t)b * (5 * Dn);
    const __nv_bfloat16* sh = g_s_hi + (size_t)b * (Fn * Dn);
    const __nv_bfloat16* sl = g_s_lo + (size_t)b * (Fn * Dn);
    __nv_bfloat16* ch = g_c_hi + (size_t)b * CINn + Fn * Dn;
    __nv_bfloat16* cl = g_c_lo + (size_t)b * CINn + Fn * Dn;
    float sv[Fn];
    #pragma unroll
    for (int j = 0; j < Fn; j++)
        sv[j] = __bfloat162float(sh[j * Dn + t]) + __bfloat162float(sl[j * Dn + t]);
    int p = 0;
    #pragma unroll
    for (int i = 0; i < 5; i++) {
        float vi = vid[i * Dn + t];
        #pragma unroll
        for (int j = i + 1; j < 6; j++) {
            float v = vi * sv[j];
            __nv_bfloat16 hi, lo;
            split_bf16(v, hi, lo);
            ch[p * Dn + t] = hi;
            cl[p * Dn + t] = lo;
            p++;
        }
    }
}

// ---------------- weight prep kernels ----------------------------------------
__global__ __launch_bounds__(256) void k_wsplit(
    const float* __restrict__ W, __nv_bfloat16* __restrict__ Th,
    __nv_bfloat16* __restrict__ Tl, int K, int N)
{
    int idx = blockIdx.x * 256 + threadIdx.x;
    if (idx >= K * N) return;
    int k = idx / N, n = idx - k * N;
    float v = W[idx];
    __nv_bfloat16 hi, lo;
    split_bf16(v, hi, lo);
    Th[(size_t)n * K + k] = hi;
    Tl[(size_t)n * K + k] = lo;
}
// gnn_W[h][i][o] -> [n=h*32+o][k=i]
__global__ __launch_bounds__(256) void k_wgnn(const float* __restrict__ W)
{
    int idx = blockIdx.x * 256 + threadIdx.x;
    if (idx >= 4 * 128 * 32) return;
    int h = idx >> 12, rem = idx & 4095;
    int i = rem >> 5, o = rem & 31;
    float v = W[idx];
    __nv_bfloat16 hi, lo;
    split_bf16(v, hi, lo);
    int n = h * 32 + o;
    g_wg_hi[n * 128 + i] = hi;
    g_wg_lo[n * 128 + i] = lo;
}
// bi_W[f][d][e] -> [f][n=e][k=d]
__global__ __launch_bounds__(256) void k_wbi(const float* __restrict__ W)
{
    int idx = blockIdx.x * 256 + threadIdx.x;
    if (idx >= 5 * 128 * 128) return;
    int f = idx >> 14, rem = idx & 16383;
    int d = rem >> 7, e = rem & 127;
    float v = W[idx];
    __nv_bfloat16 hi, lo;
    split_bf16(v, hi, lo);
    g_wb_hi[(f << 14) + e * 128 + d] = hi;
    g_wb_lo[(f << 14) + e * 128 + d] = lo;
}

// ---------------- bf16-split GEMM via mma.sync (HMMA) ------------------------
// D = A @ B^T; A[M,K] pitch lda, B[N,K] pitch K; z-batched via az/bz/cz.
// modes: 0 = raw fp32 out; 1 = bias+bn+gelu -> bf16 hi/lo; 2 = same -> fp32.
#define BM 128
#define BN 128
#define BK 32
#define ROWB 80u
#define OFF_AH 0u
#define OFF_AL 10240u
#define OFF_BH 20480u
#define OFF_BL 30720u
#define STAGEB 40960u
#define SMEM_MMA (2 * STAGEB)

__global__ __launch_bounds__(256, 1) void k_mma(
    const __nv_bfloat16* __restrict__ Ah, const __nv_bfloat16* __restrict__ Al,
    const __nv_bfloat16* __restrict__ Bh, const __nv_bfloat16* __restrict__ Bl,
    int K, int lda, long az, long bz, long cz,
    float* __restrict__ outf, __nv_bfloat16* __restrict__ oh,
    __nv_bfloat16* __restrict__ ol, int ldc,
    const float* __restrict__ bias, const float* __restrict__ bng,
    const float* __restrict__ bnb, int mode)
{
    extern __shared__ char smem[];
    const uint32_t sbase = smem_u32(smem);
    const int tid = threadIdx.x;
    const int lane = tid & 31, wid = tid >> 5;
    const int wm = wid >> 2, wn = wid & 3;
    const int bm = blockIdx.y * BM, bn = blockIdx.x * BN;
    const int z = blockIdx.z;
    Ah += (size_t)z * az; Al += (size_t)z * az;
    Bh += (size_t)z * bz; Bl += (size_t)z * bz;

    float acc[4][4][4];
    #pragma unroll
    for (int mi = 0; mi < 4; mi++)
        #pragma unroll
        for (int ni = 0; ni < 4; ni++)
            #pragma unroll
            for (int q = 0; q < 4; q++) acc[mi][ni][q] = 0.f;

    const uint32_t a_base = (uint32_t)(wm * 64 + (lane & 15)) * ROWB + (uint32_t)((lane >> 4) * 16);
    const uint32_t b_base = (uint32_t)(wn * 32 + (lane & 7) + ((lane >> 4) << 3)) * ROWB
                          + (uint32_t)(((lane >> 3) & 1) * 16);

    const int nIter = K / BK;

    auto load_stage = [&](int buf, int k0) {
        uint32_t base = sbase + (uint32_t)buf * STAGEB;
        #pragma unroll
        for (int half = 0; half < 2; half++) {
            int e = tid + half * 256;
            int r = e >> 2, c = e & 3;
            uint32_t off = (uint32_t)r * ROWB + (uint32_t)c * 16;
            size_t sa = (size_t)(bm + r) * lda + k0 + c * 8;
            size_t sbv = (size_t)(bn + r) * K + k0 + c * 8;
            cp16(base + OFF_AH + off, Ah + sa);
            cp16(base + OFF_AL + off, Al + sa);
            cp16(base + OFF_BH + off, Bh + sbv);
            cp16(base + OFF_BL + off, Bl + sbv);
        }
    };

    load_stage(0, 0);
    cp_commit();

    for (int it = 0; it < nIter; it++) {
        if (it + 1 < nIter) {
            load_stage((it + 1) & 1, (it + 1) * BK);
            cp_commit();
            cp_wait<1>();
        } else {
            cp_wait<0>();
        }
        __syncthreads();

        uint32_t base = sbase + (uint32_t)(it & 1) * STAGEB;
        #pragma unroll
        for (int ks = 0; ks < 2; ks++) {
            uint32_t koff = (uint32_t)ks * 32;
            uint32_t ah[4][4], al[4][4], bh[2][4], bl[2][4];
            #pragma unroll
            for (int mi = 0; mi < 4; mi++) {
                uint32_t ao = a_base + (uint32_t)mi * 16 * ROWB + koff;
                ldsm4(ah[mi], base + OFF_AH + ao);
                ldsm4(al[mi], base + OFF_AL + ao);
            }
            #pragma unroll
            for (int nq = 0; nq < 2; nq++) {
                uint32_t bo = b_base + (uint32_t)nq * 16 * ROWB + koff;
                ldsm4(bh[nq], base + OFF_BH + bo);
                ldsm4(bl[nq], base + OFF_BL + bo);
            }
            #pragma unroll
            for (int mi = 0; mi < 4; mi++) {
                #pragma unroll
                for (int ni = 0; ni < 4; ni++) {
                    const uint32_t* bhp = &bh[ni >> 1][(ni & 1) * 2];
                    const uint32_t* blp = &bl[ni >> 1][(ni & 1) * 2];
                    mma_bf16(acc[mi][ni], ah[mi], bhp);
                    mma_bf16(acc[mi][ni], ah[mi], blp);
                    mma_bf16(acc[mi][ni], al[mi], bhp);
                }
            }
        }
        __syncthreads();
    }

    const float bnscale = 0.999995000037499688f;  // 1/sqrt(1+1e-5)
    #pragma unroll
    for (int ni = 0; ni < 4; ni++) {
        int col = bn + wn * 32 + ni * 8 + (lane & 3) * 2;
        float bi0 = 0.f, bi1 = 0.f, g0 = 1.f, g1 = 1.f, bb0 = 0.f, bb1 = 0.f;
        if (mode != 0) {
            bi0 = bias[col];             bi1 = bias[col + 1];
            g0 = bng[col] * bnscale;     g1 = bng[col + 1] * bnscale;
            bb0 = bnb[col];              bb1 = bnb[col + 1];
        }
        #pragma unroll
        for (int mi = 0; mi < 4; mi++) {
            int r0 = bm + wm * 64 + mi * 16 + (lane >> 2);
            #pragma unroll
            for (int half = 0; half < 2; half++) {
                int row = r0 + half * 8;
                float v0 = acc[mi][ni][half * 2 + 0];
                float v1 = acc[mi][ni][half * 2 + 1];
                if (mode == 0) {
                    outf[(size_t)z * cz + (size_t)row * ldc + col]     = v0;
                    outf[(size_t)z * cz + (size_t)row * ldc + col + 1] = v1;
                    continue;
                }
                v0 = (v0 + bi0) * g0 + bb0;
                v1 = (v1 + bi1) * g1 + bb1;
                v0 = 0.5f * v0 * (1.f + erff(v0 * 0.70710678118654752f));
                v1 = 0.5f * v1 * (1.f + erff(v1 * 0.70710678118654752f));
                if (mode == 2) {
                    outf[(size_t)row * ldc + col]     = v0;
                    outf[(size_t)row * ldc + col + 1] = v1;
                } else {
                    __nv_bfloat16 h0, l0, h1, l1;
                    split_bf16(v0, h0, l0);
                    split_bf16(v1, h1, l1);
                    oh[(size_t)row * ldc + col]     = h0;
                    oh[(size_t)row * ldc + col + 1] = h1;
                    ol[(size_t)row * ldc + col]     = l0;
                    ol[(size_t)row * ldc + col + 1] = l1;
                }
            }
        }
    }
}

// ---------------- K5: final dot + sigmoid ------------------------------------
__global__ __launch_bounds__(256) void k_final(
    const float* __restrict__ w3, const float* __restrict__ b3,
    float* __restrict__ out)
{
    int warp = threadIdx.x >> 5, lane = threadIdx.x & 31;
    int b = blockIdx.x * 8 + warp;
    const float* hh = g_h2 + (size_t)b * H2N;
    float acc = 0.f;
    #pragma unroll
    for (int i = 0; i < 8; i++) acc = fmaf(hh[lane + i * 32], w3[lane + i * 32], acc);
    #pragma unroll
    for (int o = 16; o; o >>= 1) acc += __shfl_xor_sync(0xffffffffu, acc, o);
    if (!lane) out[b] = 1.f / (1.f + expf(-(acc + b3[0])));
}

// ---------------- launch -----------------------------------------------------
extern "C" void kernel_launch(void* const* d_in, const int* in_sizes, int n_in,
                              void* d_out, int out_size)
{
    const int*   item_id  = (const int*)  d_in[0];
    const float* item_mm  = (const float*)d_in[1];
    const int*   likes    = (const int*)  d_in[2];
    const int*   views    = (const int*)  d_in[3];
    const int*   item_seq = (const int*)  d_in[4];
    const float* item_emb = (const float*)d_in[5];
    const float* cate_emb = (const float*)d_in[6];
    const float* mm_w     = (const float*)d_in[7];
    const float* mm_b     = (const float*)d_in[8];
    const float* ln_g     = (const float*)d_in[9];
    const float* ln_b     = (const float*)d_in[10];
    const float* gnn_W    = (const float*)d_in[11];
    const float* gnn_a    = (const float*)d_in[12];
    const float* se_w1    = (const float*)d_in[13];
    const float* se_b1    = (const float*)d_in[14];
    const float* se_w2    = (const float*)d_in[15];
    const float* se_b2    = (const float*)d_in[16];
    const float* bi_W     = (const float*)d_in[17];
    const float* w1       = (const float*)d_in[18];
    const float* b1       = (const float*)d_in[19];
    const float* bn1g     = (const float*)d_in[20];
    const float* bn1b     = (const float*)d_in[21];
    const float* w2       = (const float*)d_in[22];
    const float* b2       = (const float*)d_in[23];
    const float* bn2g     = (const float*)d_in[24];
    const float* bn2b     = (const float*)d_in[25];
    const float* w3       = (const float*)d_in[26];
    const float* b3       = (const float*)d_in[27];
    float* out = (float*)d_out;

    float *php, *pv, *ph2;
    __nv_bfloat16 *pxh, *pxl, *psh, *psl, *pch, *pcl, *ph1h, *ph1l;
    __nv_bfloat16 *pw1h, *pw1l, *pw2h, *pw2l, *pwgh, *pwgl, *pwbh, *pwbl;
    cudaGetSymbolAddress((void**)&php,  g_hp);
    cudaGetSymbolAddress((void**)&pv,   g_vid);
    cudaGetSymbolAddress((void**)&ph2,  g_h2);
    cudaGetSymbolAddress((void**)&pxh,  g_x_hi);
    cudaGetSymbolAddress((void**)&pxl,  g_x_lo);
    cudaGetSymbolAddress((void**)&psh,  g_s_hi);
    cudaGetSymbolAddress((void**)&psl,  g_s_lo);
    cudaGetSymbolAddress((void**)&pch,  g_c_hi);
    cudaGetSymbolAddress((void**)&pcl,  g_c_lo);
    cudaGetSymbolAddress((void**)&ph1h, g_h1_hi);
    cudaGetSymbolAddress((void**)&ph1l, g_h1_lo);
    cudaGetSymbolAddress((void**)&pw1h, g_w1t_hi);
    cudaGetSymbolAddress((void**)&pw1l, g_w1t_lo);
    cudaGetSymbolAddress((void**)&pw2h, g_w2t_hi);
    cudaGetSymbolAddress((void**)&pw2l, g_w2t_lo);
    cudaGetSymbolAddress((void**)&pwgh, g_wg_hi);
    cudaGetSymbolAddress((void**)&pwgl, g_wg_lo);
    cudaGetSymbolAddress((void**)&pwbh, g_wb_hi);
    cudaGetSymbolAddress((void**)&pwbl, g_wb_lo);

    cudaFuncSetAttribute(k_mma, cudaFuncAttributeMaxDynamicSharedMemorySize, SMEM_MMA);

    // weight prep
    k_wsplit<<<(CINn * H1N + 255) / 256, 256>>>(w1, pw1h, pw1l, CINn, H1N);
    k_wsplit<<<(H1N * H2N + 255) / 256, 256>>>(w2, pw2h, pw2l, H1N, H2N);
    k_wgnn<<<(4 * 128 * 32 + 255) / 256, 256>>>(gnn_W);
    k_wbi<<<(5 * 128 * 128 + 255) / 256, 256>>>(bi_W);

    k_features<<<Bn, 128>>>(item_id, item_mm, likes, views, item_seq,
                            item_emb, cate_emb, mm_w, mm_b, ln_g, ln_b);

    // hp = x @ Wgnn^T : M = B*6 = 98304, N = 128, K = 128
    {
        dim3 grid(1, (Bn * Fn) / BM, 1);
        k_mma<<<grid, 256, SMEM_MMA>>>(pxh, pxl, pwgh, pwgl, Dn, Dn, 0, 0, 0,
                                       php, nullptr, nullptr, Dn,
                                       nullptr, nullptr, nullptr, 0);
    }

    k_gnn<<<Bn, 128>>>(gnn_a, se_w1, se_b1, se_w2, se_b2);

    // vid[b,f,:] = s[b,f,:] @ bi_W[f]^T : z-batched over 5 fields
    {
        dim3 grid(1, Bn / BM, 5);
        k_mma<<<grid, 256, SMEM_MMA>>>(psh, psl, pwbh, pwbl, Dn, Fn * Dn,
                                       Dn, (long)Dn * Dn, Dn,
                                       pv, nullptr, nullptr, 5 * Dn,
                                       nullptr, nullptr, nullptr, 0);
    }
    k_pairs<<<Bn, 128>>>();

    // layer 1: c @ w1 (+bias,bn,gelu) -> h1 (bf16 hi/lo)
    {
        dim3 grid(H1N / BN, Bn / BM, 1);
        k_mma<<<grid, 256, SMEM_MMA>>>(pch, pcl, pw1h, pw1l, CINn, CINn, 0, 0, 0,
                                       nullptr, ph1h, ph1l, H1N,
                                       b1, bn1g, bn1b, 1);
    }
    // layer 2: h1 @ w2 (+bias,bn,gelu) -> h2 (fp32)
    {
        dim3 grid(H2N / BN, Bn / BM, 1);
        k_mma<<<grid, 256, SMEM_MMA>>>(ph1h, ph1l, pw2h, pw2l, H1N, H1N, 0, 0, 0,
                                       ph2, nullptr, nullptr, H2N,
                                       b2, bn2g, bn2b, 2);
    }
    k_final<<<Bn / 8, 256>>>(w3, b3, out);
}

// round 5
// speedup vs baseline: 1.4150x; 1.4150x over previous
#include <cuda_runtime.h>
#include <cuda_bf16.h>
#include <math.h>
#include <stdint.h>

#define Bn 16384
#define Ln 50
#define Dn 128
#define Fn 6
#define CINn 2688
#define H1N 512
#define H2N 256

// ---------------- scratch (static device globals) ---------------------------
__device__ __align__(16) float g_x  [Bn * Fn * Dn];
__device__ __align__(16) float g_s  [Bn * Fn * Dn];
__device__ __align__(16) float g_vid[Bn * 5 * Dn];
__device__ __align__(16) __nv_bfloat16 g_c_hi[Bn * CINn];
__device__ __align__(16) __nv_bfloat16 g_c_lo[Bn * CINn];
__device__ __align__(16) __nv_bfloat16 g_h1_hi[Bn * H1N];
__device__ __align__(16) __nv_bfloat16 g_h1_lo[Bn * H1N];
__device__ __align__(16) float g_h2 [Bn * H2N];
__device__ __align__(16) __nv_bfloat16 g_w1t_hi[H1N * CINn];
__device__ __align__(16) __nv_bfloat16 g_w1t_lo[H1N * CINn];
__device__ __align__(16) __nv_bfloat16 g_w2t_hi[H2N * H1N];
__device__ __align__(16) __nv_bfloat16 g_w2t_lo[H2N * H1N];

// ---------------- PTX helpers (sm_80-level only; no 'a'-suffix features) -----
__device__ __forceinline__ uint32_t smem_u32(const void* p) {
    uint32_t a;
    asm("{ .reg .u64 t; cvta.to.shared.u64 t, %1; cvt.u32.u64 %0, t; }" : "=r"(a) : "l"(p));
    return a;
}
__device__ __forceinline__ void cp16(uint32_t dst, const void* src) {
    asm volatile("cp.async.cg.shared.global [%0], [%1], 16;" :: "r"(dst), "l"(src));
}
__device__ __forceinline__ void cp_commit() {
    asm volatile("cp.async.commit_group;" ::: "memory");
}
template <int N>
__device__ __forceinline__ void cp_wait() {
    asm volatile("cp.async.wait_group %0;" :: "n"(N) : "memory");
}
__device__ __forceinline__ void ldsm4(uint32_t* r, uint32_t addr) {
    asm volatile("ldmatrix.sync.aligned.m8n8.x4.shared.b16 {%0,%1,%2,%3}, [%4];"
                 : "=r"(r[0]), "=r"(r[1]), "=r"(r[2]), "=r"(r[3]) : "r"(addr));
}
__device__ __forceinline__ void mma_bf16(float* d, const uint32_t* a, const uint32_t* b) {
    asm volatile(
        "mma.sync.aligned.m16n8k16.row.col.f32.bf16.bf16.f32 "
        "{%0,%1,%2,%3}, {%4,%5,%6,%7}, {%8,%9}, {%0,%1,%2,%3};"
        : "+f"(d[0]), "+f"(d[1]), "+f"(d[2]), "+f"(d[3])
        : "r"(a[0]), "r"(a[1]), "r"(a[2]), "r"(a[3]), "r"(b[0]), "r"(b[1]));
}

// ---------------- K1: features -> x[b, 6, 128] ------------------------------
__global__ __launch_bounds__(128) void k_features(
    const int* __restrict__ item_id, const float* __restrict__ item_mm,
    const int* __restrict__ likes, const int* __restrict__ views,
    const int* __restrict__ item_seq, const float* __restrict__ item_emb,
    const float* __restrict__ cate_emb, const float* __restrict__ mm_w,
    const float* __restrict__ mm_b, const float* __restrict__ ln_g,
    const float* __restrict__ ln_b)
{
    int b = blockIdx.x, t = threadIdx.x;
    int lane = t & 31, w = t >> 5;
    __shared__ float sm[Dn];
    __shared__ float red[8];

    sm[t] = item_mm[b * Dn + t];
    __syncthreads();

    float y = mm_b[t];
    #pragma unroll 16
    for (int i = 0; i < Dn; i++) y = fmaf(sm[i], mm_w[i * Dn + t], y);

    float s1 = y, s2 = y * y;
    #pragma unroll
    for (int o = 16; o; o >>= 1) {
        s1 += __shfl_xor_sync(0xffffffffu, s1, o);
        s2 += __shfl_xor_sync(0xffffffffu, s2, o);
    }
    if (!lane) { red[w] = s1; red[4 + w] = s2; }
    __syncthreads();
    float mu = (red[0] + red[1] + red[2] + red[3]) * (1.f / Dn);
    float m2 = (red[4] + red[5] + red[6] + red[7]) * (1.f / Dn);
    float var = m2 - mu * mu;
    float yn = (y - mu) * rsqrtf(var + 1e-5f) * ln_g[t] + ln_b[t];
    float img = 0.5f * yn * (1.f + erff(yn * 0.70710678118654752f));

    float hs = 0.f, cnt = 0.f;
    const int* seq = item_seq + b * Ln;
    for (int l = 0; l < Ln; l++) {
        int id = seq[l];
        if (id != 0) { hs += item_emb[(size_t)id * Dn + t]; cnt += 1.f; }
    }
    float hist = hs / fmaxf(cnt, 1.f);

    float* xb = g_x + (size_t)b * (Fn * Dn);
    xb[0 * Dn + t] = 0.f;
    xb[1 * Dn + t] = cate_emb[likes[b] * Dn + t];
    xb[2 * Dn + t] = cate_emb[views[b] * Dn + t];
    xb[3 * Dn + t] = item_emb[(size_t)item_id[b] * Dn + t];
    xb[4 * Dn + t] = img;
    xb[5 * Dn + t] = hist;
}

// ---------------- K2: GAT + SE -> c_hi/c_lo[:, :768] and s -------------------
// hp inner loop: W chunk-hoisted to registers (128 LDG/thread instead of 768),
// x read as float4 LDS broadcasts (192 LDS instead of 768).
__global__ __launch_bounds__(128) void k_gnn(
    const float* __restrict__ gnn_W, const float* __restrict__ gnn_a,
    const float* __restrict__ se_w1, const float* __restrict__ se_b1,
    const float* __restrict__ se_w2, const float* __restrict__ se_b2)
{
    int b = blockIdx.x, t = threadIdx.x;
    int h = t >> 5, lane = t & 31;
    __shared__ float xs[Fn * Dn];
    __shared__ float red[4 * Fn];

    const float* xb = g_x + (size_t)b * Fn * Dn;
    #pragma unroll
    for (int n = 0; n < Fn; n++) xs[n * Dn + t] = xb[n * Dn + t];
    __syncthreads();

    // hp[n] = sum_i xs[n][i] * W[h][i][lane]
    float hp[Fn];
    #pragma unroll
    for (int n = 0; n < Fn; n++) hp[n] = 0.f;
    const float* Wh = gnn_W + h * (Dn * 32) + lane;
    #pragma unroll
    for (int c = 0; c < 4; c++) {
        float w[32];
        #pragma unroll
        for (int q = 0; q < 32; q++) w[q] = Wh[(c * 32 + q) * 32];
        #pragma unroll
        for (int n = 0; n < Fn; n++) {
            const float4* xv = reinterpret_cast<const float4*>(&xs[n * Dn + c * 32]);
            float a = hp[n];
            #pragma unroll
            for (int q8 = 0; q8 < 8; q8++) {
                float4 v = xv[q8];
                a = fmaf(v.x, w[q8 * 4 + 0], a);
                a = fmaf(v.y, w[q8 * 4 + 1], a);
                a = fmaf(v.z, w[q8 * 4 + 2], a);
                a = fmaf(v.w, w[q8 * 4 + 3], a);
            }
            hp[n] = a;
        }
    }

    float a1 = gnn_a[h * 64 + lane];
    float a2 = gnn_a[h * 64 + 32 + lane];
    float ei[Fn], ej[Fn];
    #pragma unroll
    for (int n = 0; n < Fn; n++) {
        float v1 = hp[n] * a1, v2 = hp[n] * a2;
        #pragma unroll
        for (int o = 16; o; o >>= 1) {
            v1 += __shfl_xor_sync(0xffffffffu, v1, o);
            v2 += __shfl_xor_sync(0xffffffffu, v2, o);
        }
        ei[n] = v1; ej[n] = v2;
    }

    float gnn[Fn];
    #pragma unroll
    for (int n = 0; n < Fn; n++) {
        float em[Fn], mx = -1e30f;
        #pragma unroll
        for (int m = 0; m < Fn; m++) {
            float e = ei[n] + ej[m];
            e = e > 0.f ? e : 0.2f * e;
            em[m] = e; mx = fmaxf(mx, e);
        }
        float ss = 0.f;
        #pragma unroll
        for (int m = 0; m < Fn; m++) { em[m] = expf(em[m] - mx); ss += em[m]; }
        float inv = 1.f / ss, acc = 0.f;
        #pragma unroll
        for (int m = 0; m < Fn; m++) acc = fmaf(em[m], hp[m], acc);
        float hn = acc * inv + xs[n * Dn + t];
        gnn[n] = hn > 0.f ? hn : expm1f(hn);
    }

    #pragma unroll
    for (int n = 0; n < Fn; n++) {
        float v = gnn[n];
        #pragma unroll
        for (int o = 16; o; o >>= 1) v += __shfl_xor_sync(0xffffffffu, v, o);
        if (!lane) red[h * Fn + n] = v;
    }
    __syncthreads();

    float wv[Fn];
    {
        float z[Fn];
        #pragma unroll
        for (int n = 0; n < Fn; n++)
            z[n] = (red[0 * Fn + n] + red[1 * Fn + n] + red[2 * Fn + n] + red[3 * Fn + n]) * (1.f / Dn);
        float a[3];
        #pragma unroll
        for (int k = 0; k < 3; k++) {
            float v = se_b1[k];
            #pragma unroll
            for (int n = 0; n < Fn; n++) v = fmaf(z[n], se_w1[n * 3 + k], v);
            a[k] = fmaxf(v, 0.f);
        }
        #pragma unroll
        for (int f = 0; f < Fn; f++) {
            float v = se_b2[f];
            #pragma unroll
            for (int k = 0; k < 3; k++) v = fmaf(a[k], se_w2[k * 6 + f], v);
            wv[f] = 1.f / (1.f + expf(-v));
        }
    }

    __nv_bfloat16* ch = g_c_hi + (size_t)b * CINn;
    __nv_bfloat16* cl = g_c_lo + (size_t)b * CINn;
    float* sb = g_s + (size_t)b * Fn * Dn;
    #pragma unroll
    for (int n = 0; n < Fn; n++) {
        float v = gnn[n];
        __nv_bfloat16 hi = __float2bfloat16(v);
        ch[n * Dn + t] = hi;
        cl[n * Dn + t] = __float2bfloat16(v - __bfloat162float(hi));
        sb[n * Dn + t] = v * wv[n];
    }
}

// ---------------- fp32 SGEMM for the bilinear (small) ------------------------
#define BMg 128
#define BNg 64
#define BKg 16
__global__ __launch_bounds__(256) void k_gemm(
    const float* __restrict__ A, int lda, long saz,
    const float* __restrict__ Wt, int ldb, long swz,
    float* __restrict__ Co, int ldc, long scz, int K)
{
    A  += (size_t)blockIdx.z * saz;
    Wt += (size_t)blockIdx.z * swz;
    Co += (size_t)blockIdx.z * scz;
    int bm = blockIdx.y * BMg, bn = blockIdx.x * BNg;
    int tid = threadIdx.x;
    int tx = tid & 15, ty = tid >> 4;

    __shared__ float As[BKg][BMg + 4];
    __shared__ float Bs[BKg][BNg + 4];

    float acc[8][4];
    #pragma unroll
    for (int i = 0; i < 8; i++)
        #pragma unroll
        for (int j = 0; j < 4; j++) acc[i][j] = 0.f;

    for (int k0 = 0; k0 < K; k0 += BKg) {
        #pragma unroll
        for (int ii = 0; ii < 2; ii++) {
            int e = tid + ii * 256;
            int m = e >> 2, k4 = (e & 3) * 4;
            const float4 v = *reinterpret_cast<const float4*>(&A[(size_t)(bm + m) * lda + k0 + k4]);
            As[k4 + 0][m] = v.x; As[k4 + 1][m] = v.y;
            As[k4 + 2][m] = v.z; As[k4 + 3][m] = v.w;
        }
        {
            int kk = tid >> 4, c4 = (tid & 15) * 4;
            const float4 v = *reinterpret_cast<const float4*>(&Wt[(size_t)(k0 + kk) * ldb + bn + c4]);
            Bs[kk][c4 + 0] = v.x; Bs[kk][c4 + 1] = v.y;
            Bs[kk][c4 + 2] = v.z; Bs[kk][c4 + 3] = v.w;
        }
        __syncthreads();
        #pragma unroll
        for (int kk = 0; kk < BKg; kk++) {
            float a[8], bb4[4];
            #pragma unroll
            for (int i = 0; i < 8; i++) a[i] = As[kk][ty * 8 + i];
            #pragma unroll
            for (int j = 0; j < 4; j++) bb4[j] = Bs[kk][tx * 4 + j];
            #pragma unroll
            for (int i = 0; i < 8; i++)
                #pragma unroll
                for (int j = 0; j < 4; j++) acc[i][j] = fmaf(a[i], bb4[j], acc[i][j]);
        }
        __syncthreads();
    }
    #pragma unroll
    for (int i = 0; i < 8; i++) {
        int row = bm + ty * 8 + i;
        #pragma unroll
        for (int j = 0; j < 4; j++)
            Co[(size_t)row * ldc + bn + tx * 4 + j] = acc[i][j];
    }
}

// ---------------- K4: bilinear pairs -> c_hi/c_lo[:, 768:] -------------------
__global__ __launch_bounds__(128) void k_pairs()
{
    int b = blockIdx.x, t = threadIdx.x;
    const float* vid = g_vid + (size_t)b * (5 * Dn);
    const float* sb  = g_s   + (size_t)b * (Fn * Dn);
    __nv_bfloat16* ch = g_c_hi + (size_t)b * CINn + Fn * Dn;
    __nv_bfloat16* cl = g_c_lo + (size_t)b * CINn + Fn * Dn;
    int p = 0;
    #pragma unroll
    for (int i = 0; i < 5; i++) {
        float vi = vid[i * Dn + t];
        #pragma unroll
        for (int j = i + 1; j < 6; j++) {
            float v = vi * sb[j * Dn + t];
            __nv_bfloat16 hi = __float2bfloat16(v);
            ch[p * Dn + t] = hi;
            cl[p * Dn + t] = __float2bfloat16(v - __bfloat162float(hi));
            p++;
        }
    }
}

// ---------------- weight transpose + bf16 split ------------------------------
__global__ __launch_bounds__(256) void k_wsplit(
    const float* __restrict__ W, __nv_bfloat16* __restrict__ Th,
    __nv_bfloat16* __restrict__ Tl, int K, int N)
{
    int idx = blockIdx.x * 256 + threadIdx.x;
    if (idx >= K * N) return;
    int k = idx / N, n = idx - k * N;
    float v = W[idx];
    __nv_bfloat16 hi = __float2bfloat16(v);
    Th[(size_t)n * K + k] = hi;
    Tl[(size_t)n * K + k] = __float2bfloat16(v - __bfloat162float(hi));
}

// ---------------- bf16-split GEMM via mma.sync (HMMA) + fused epilogue -------
#define BM 128
#define BN 128
#define BK 32
#define ROWB 80u
#define OFF_AH 0u
#define OFF_AL 10240u
#define OFF_BH 20480u
#define OFF_BL 30720u
#define STAGEB 40960u
#define SMEM_MMA (2 * STAGEB)

__global__ __launch_bounds__(256, 1) void k_mma(
    const __nv_bfloat16* __restrict__ Ah, const __nv_bfloat16* __restrict__ Al,
    const __nv_bfloat16* __restrict__ Bh, const __nv_bfloat16* __restrict__ Bl,
    int K,
    float* __restrict__ outf, __nv_bfloat16* __restrict__ oh,
    __nv_bfloat16* __restrict__ ol, int ldc,
    const float* __restrict__ bias, const float* __restrict__ bng,
    const float* __restrict__ bnb, int mode)
{
    extern __shared__ char smem[];
    const uint32_t sbase = smem_u32(smem);
    const int tid = threadIdx.x;
    const int lane = tid & 31, wid = tid >> 5;
    const int wm = wid >> 2, wn = wid & 3;
    const int bm = blockIdx.y * BM, bn = blockIdx.x * BN;

    float acc[4][4][4];
    #pragma unroll
    for (int mi = 0; mi < 4; mi++)
        #pragma unroll
        for (int ni = 0; ni < 4; ni++)
            #pragma unroll
            for (int q = 0; q < 4; q++) acc[mi][ni][q] = 0.f;

    const uint32_t a_base = (uint32_t)(wm * 64 + (lane & 15)) * ROWB + (uint32_t)((lane >> 4) * 16);
    const uint32_t b_base = (uint32_t)(wn * 32 + (lane & 7) + ((lane >> 4) << 3)) * ROWB
                          + (uint32_t)(((lane >> 3) & 1) * 16);

    const int nIter = K / BK;

    auto load_stage = [&](int buf, int k0) {
        uint32_t base = sbase + (uint32_t)buf * STAGEB;
        #pragma unroll
        for (int half = 0; half < 2; half++) {
            int e = tid + half * 256;
            int r = e >> 2, c = e & 3;
            uint32_t off = (uint32_t)r * ROWB + (uint32_t)c * 16;
            size_t sa = (size_t)(bm + r) * K + k0 + c * 8;
            size_t sbv = (size_t)(bn + r) * K + k0 + c * 8;
            cp16(base + OFF_AH + off, Ah + sa);
            cp16(base + OFF_AL + off, Al + sa);
            cp16(base + OFF_BH + off, Bh + sbv);
            cp16(base + OFF_BL + off, Bl + sbv);
        }
    };

    load_stage(0, 0);
    cp_commit();

    for (int it = 0; it < nIter; it++) {
        if (it + 1 < nIter) {
            load_stage((it + 1) & 1, (it + 1) * BK);
            cp_commit();
            cp_wait<1>();
        } else {
            cp_wait<0>();
        }
        __syncthreads();

        uint32_t base = sbase + (uint32_t)(it & 1) * STAGEB;
        #pragma unroll
        for (int ks = 0; ks < 2; ks++) {
            uint32_t koff = (uint32_t)ks * 32;
            uint32_t ah[4][4], al[4][4], bh[2][4], bl[2][4];
            #pragma unroll
            for (int mi = 0; mi < 4; mi++) {
                uint32_t ao = a_base + (uint32_t)mi * 16 * ROWB + koff;
                ldsm4(ah[mi], base + OFF_AH + ao);
                ldsm4(al[mi], base + OFF_AL + ao);
            }
            #pragma unroll
            for (int nq = 0; nq < 2; nq++) {
                uint32_t bo = b_base + (uint32_t)nq * 16 * ROWB + koff;
                ldsm4(bh[nq], base + OFF_BH + bo);
                ldsm4(bl[nq], base + OFF_BL + bo);
            }
            #pragma unroll
            for (int mi = 0; mi < 4; mi++) {
                #pragma unroll
                for (int ni = 0; ni < 4; ni++) {
                    const uint32_t* bhp = &bh[ni >> 1][(ni & 1) * 2];
                    const uint32_t* blp = &bl[ni >> 1][(ni & 1) * 2];
                    mma_bf16(acc[mi][ni], ah[mi], bhp);
                    mma_bf16(acc[mi][ni], ah[mi], blp);
                    mma_bf16(acc[mi][ni], al[mi], bhp);
                }
            }
        }
        __syncthreads();
    }

    const float bnscale = 0.999995000037499688f;  // 1/sqrt(1+1e-5)
    #pragma unroll
    for (int ni = 0; ni < 4; ni++) {
        int col = bn + wn * 32 + ni * 8 + (lane & 3) * 2;
        float bi0 = bias[col],     bi1 = bias[col + 1];
        float g0 = bng[col] * bnscale, g1 = bng[col + 1] * bnscale;
        float bb0 = bnb[col],      bb1 = bnb[col + 1];
        #pragma unroll
        for (int mi = 0; mi < 4; mi++) {
            int r0 = bm + wm * 64 + mi * 16 + (lane >> 2);
            #pragma unroll
            for (int half = 0; half < 2; half++) {
                int row = r0 + half * 8;
                float v0 = acc[mi][ni][half * 2 + 0];
                float v1 = acc[mi][ni][half * 2 + 1];
                v0 = (v0 + bi0) * g0 + bb0;
                v1 = (v1 + bi1) * g1 + bb1;
                v0 = 0.5f * v0 * (1.f + erff(v0 * 0.70710678118654752f));
                v1 = 0.5f * v1 * (1.f + erff(v1 * 0.70710678118654752f));
                if (mode == 2) {
                    outf[(size_t)row * ldc + col]     = v0;
                    outf[(size_t)row * ldc + col + 1] = v1;
                } else {
                    __nv_bfloat16 h0 = __float2bfloat16(v0);
                    __nv_bfloat16 h1 = __float2bfloat16(v1);
                    oh[(size_t)row * ldc + col]     = h0;
                    oh[(size_t)row * ldc + col + 1] = h1;
                    ol[(size_t)row * ldc + col]     = __float2bfloat16(v0 - __bfloat162float(h0));
                    ol[(size_t)row * ldc + col + 1] = __float2bfloat16(v1 - __bfloat162float(h1));
                }
            }
        }
    }
}

// ---------------- K5: final dot + sigmoid ------------------------------------
__global__ __launch_bounds__(256) void k_final(
    const float* __restrict__ w3, const float* __restrict__ b3,
    float* __restrict__ out)
{
    int warp = threadIdx.x >> 5, lane = threadIdx.x & 31;
    int b = blockIdx.x * 8 + warp;
    const float* hh = g_h2 + (size_t)b * H2N;
    float acc = 0.f;
    #pragma unroll
    for (int i = 0; i < 8; i++) acc = fmaf(hh[lane + i * 32], w3[lane + i * 32], acc);
    #pragma unroll
    for (int o = 16; o; o >>= 1) acc += __shfl_xor_sync(0xffffffffu, acc, o);
    if (!lane) out[b] = 1.f / (1.f + expf(-(acc + b3[0])));
}

// ---------------- launch -----------------------------------------------------
extern "C" void kernel_launch(void* const* d_in, const int* in_sizes, int n_in,
                              void* d_out, int out_size)
{
    const int*   item_id  = (const int*)  d_in[0];
    const float* item_mm  = (const float*)d_in[1];
    const int*   likes    = (const int*)  d_in[2];
    const int*   views    = (const int*)  d_in[3];
    const int*   item_seq = (const int*)  d_in[4];
    const float* item_emb = (const float*)d_in[5];
    const float* cate_emb = (const float*)d_in[6];
    const float* mm_w     = (const float*)d_in[7];
    const float* mm_b     = (const float*)d_in[8];
    const float* ln_g     = (const float*)d_in[9];
    const float* ln_b     = (const float*)d_in[10];
    const float* gnn_W    = (const float*)d_in[11];
    const float* gnn_a    = (const float*)d_in[12];
    const float* se_w1    = (const float*)d_in[13];
    const float* se_b1    = (const float*)d_in[14];
    const float* se_w2    = (const float*)d_in[15];
    const float* se_b2    = (const float*)d_in[16];
    const float* bi_W     = (const float*)d_in[17];
    const float* w1       = (const float*)d_in[18];
    const float* b1       = (const float*)d_in[19];
    const float* bn1g     = (const float*)d_in[20];
    const float* bn1b     = (const float*)d_in[21];
    const float* w2       = (const float*)d_in[22];
    const float* b2       = (const float*)d_in[23];
    const float* bn2g     = (const float*)d_in[24];
    const float* bn2b     = (const float*)d_in[25];
    const float* w3       = (const float*)d_in[26];
    const float* b3       = (const float*)d_in[27];
    float* out = (float*)d_out;

    float *ps, *pv, *ph2;
    __nv_bfloat16 *pch, *pcl, *ph1h, *ph1l, *pw1h, *pw1l, *pw2h, *pw2l;
    cudaGetSymbolAddress((void**)&ps,   g_s);
    cudaGetSymbolAddress((void**)&pv,   g_vid);
    cudaGetSymbolAddress((void**)&ph2,  g_h2);
    cudaGetSymbolAddress((void**)&pch,  g_c_hi);
    cudaGetSymbolAddress((void**)&pcl,  g_c_lo);
    cudaGetSymbolAddress((void**)&ph1h, g_h1_hi);
    cudaGetSymbolAddress((void**)&ph1l, g_h1_lo);
    cudaGetSymbolAddress((void**)&pw1h, g_w1t_hi);
    cudaGetSymbolAddress((void**)&pw1l, g_w1t_lo);
    cudaGetSymbolAddress((void**)&pw2h, g_w2t_hi);
    cudaGetSymbolAddress((void**)&pw2l, g_w2t_lo);

    cudaFuncSetAttribute(k_mma, cudaFuncAttributeMaxDynamicSharedMemorySize, SMEM_MMA);

    // weight prep (bf16 split + transpose)
    k_wsplit<<<(CINn * H1N + 255) / 256, 256>>>(w1, pw1h, pw1l, CINn, H1N);
    k_wsplit<<<(H1N * H2N + 255) / 256, 256>>>(w2, pw2h, pw2l, H1N, H2N);

    k_features<<<Bn, 128>>>(item_id, item_mm, likes, views, item_seq,
                            item_emb, cate_emb, mm_w, mm_b, ln_g, ln_b);
    k_gnn<<<Bn, 128>>>(gnn_W, gnn_a, se_w1, se_b1, se_w2, se_b2);

    // bilinear: vid[b,f,:] = s[b,f,:] @ bi_W[f]
    {
        dim3 grid(Dn / BNg, Bn / BMg, 5);
        k_gemm<<<grid, 256>>>(ps, Fn * Dn, Dn, bi_W, Dn, (long)Dn * Dn,
                              pv, 5 * Dn, Dn, Dn);
    }
    k_pairs<<<Bn, 128>>>();

    // layer 1: c @ w1 (+bias,bn,gelu) -> h1 (bf16 hi/lo)
    {
        dim3 grid(H1N / BN, Bn / BM);
        k_mma<<<grid, 256, SMEM_MMA>>>(pch, pcl, pw1h, pw1l, CINn,
                                       nullptr, ph1h, ph1l, H1N,
                                       b1, bn1g, bn1b, 1);
    }
    // layer 2: h1 @ w2 (+bias,bn,gelu) -> h2 (fp32)
    {
        dim3 grid(H2N / BN, Bn / BM);
        k_mma<<<grid, 256, SMEM_MMA>>>(ph1h, ph1l, pw2h, pw2l, H1N,
                                       ph2, nullptr, nullptr, H2N,
                                       b2, bn2g, bn2b, 2);
    }
    k_final<<<Bn / 8, 256>>>(w3, b3, out);
}

// round 7
// speedup vs baseline: 1.6802x; 1.1874x over previous
#include <cuda_runtime.h>
#include <cuda_fp16.h>
#include <math.h>
#include <stdint.h>

#define Bn 16384
#define Ln 50
#define Dn 128
#define Fn 6
#define CINn 2688
#define H1N 512
#define H2N 256

// ---------------- scratch (static device globals) ---------------------------
__device__ __align__(16) float g_x  [Bn * Fn * Dn];
__device__ __align__(16) float g_s  [Bn * Fn * Dn];
__device__ __align__(16) float g_vid[Bn * 5 * Dn];
__device__ __align__(16) __half g_c  [Bn * CINn];      // fp16 activations (single)
__device__ __align__(16) __half g_h1 [Bn * H1N];
__device__ __align__(16) float g_h2 [Bn * H2N];
__device__ __align__(16) __half g_w1t_hi[H1N * CINn];  // fp16 weight hi/lo (transposed)
__device__ __align__(16) __half g_w1t_lo[H1N * CINn];
__device__ __align__(16) __half g_w2t_hi[H2N * H1N];
__device__ __align__(16) __half g_w2t_lo[H2N * H1N];

// ---------------- PTX helpers (sm_80-level only) -----------------------------
__device__ __forceinline__ uint32_t smem_u32(const void* p) {
    uint32_t a;
    asm("{ .reg .u64 t; cvta.to.shared.u64 t, %1; cvt.u32.u64 %0, t; }" : "=r"(a) : "l"(p));
    return a;
}
__device__ __forceinline__ void cp16(uint32_t dst, const void* src) {
    asm volatile("cp.async.cg.shared.global [%0], [%1], 16;" :: "r"(dst), "l"(src));
}
__device__ __forceinline__ void cp_commit() {
    asm volatile("cp.async.commit_group;" ::: "memory");
}
template <int N>
__device__ __forceinline__ void cp_wait() {
    asm volatile("cp.async.wait_group %0;" :: "n"(N) : "memory");
}
__device__ __forceinline__ void ldsm4(uint32_t* r, uint32_t addr) {
    asm volatile("ldmatrix.sync.aligned.m8n8.x4.shared.b16 {%0,%1,%2,%3}, [%4];"
                 : "=r"(r[0]), "=r"(r[1]), "=r"(r[2]), "=r"(r[3]) : "r"(addr));
}
__device__ __forceinline__ void mma_fp16(float* d, const uint32_t* a, const uint32_t* b) {
    asm volatile(
        "mma.sync.aligned.m16n8k16.row.col.f32.f16.f16.f32 "
        "{%0,%1,%2,%3}, {%4,%5,%6,%7}, {%8,%9}, {%0,%1,%2,%3};"
        : "+f"(d[0]), "+f"(d[1]), "+f"(d[2]), "+f"(d[3])
        : "r"(a[0]), "r"(a[1]), "r"(a[2]), "r"(a[3]), "r"(b[0]), "r"(b[1]));
}

// ---------------- K1: features -> x[b, 6, 128] ------------------------------
__global__ __launch_bounds__(128) void k_features(
    const int* __restrict__ item_id, const float* __restrict__ item_mm,
    const int* __restrict__ likes, const int* __restrict__ views,
    const int* __restrict__ item_seq, const float* __restrict__ item_emb,
    const float* __restrict__ cate_emb, const float* __restrict__ mm_w,
    const float* __restrict__ mm_b, const float* __restrict__ ln_g,
    const float* __restrict__ ln_b)
{
    int b = blockIdx.x, t = threadIdx.x;
    int lane = t & 31, w = t >> 5;
    __shared__ float sm[Dn];
    __shared__ float red[8];

    sm[t] = item_mm[b * Dn + t];
    __syncthreads();

    float y = mm_b[t];
    #pragma unroll 16
    for (int i = 0; i < Dn; i++) y = fmaf(sm[i], mm_w[i * Dn + t], y);

    float s1 = y, s2 = y * y;
    #pragma unroll
    for (int o = 16; o; o >>= 1) {
        s1 += __shfl_xor_sync(0xffffffffu, s1, o);
        s2 += __shfl_xor_sync(0xffffffffu, s2, o);
    }
    if (!lane) { red[w] = s1; red[4 + w] = s2; }
    __syncthreads();
    float mu = (red[0] + red[1] + red[2] + red[3]) * (1.f / Dn);
    float m2 = (red[4] + red[5] + red[6] + red[7]) * (1.f / Dn);
    float var = m2 - mu * mu;
    float yn = (y - mu) * rsqrtf(var + 1e-5f) * ln_g[t] + ln_b[t];
    float img = 0.5f * yn * (1.f + erff(yn * 0.70710678118654752f));

    float hs = 0.f, cnt = 0.f;
    const int* seq = item_seq + b * Ln;
    for (int l = 0; l < Ln; l++) {
        int id = seq[l];
        if (id != 0) { hs += item_emb[(size_t)id * Dn + t]; cnt += 1.f; }
    }
    float hist = hs / fmaxf(cnt, 1.f);

    float* xb = g_x + (size_t)b * (Fn * Dn);
    xb[0 * Dn + t] = 0.f;
    xb[1 * Dn + t] = cate_emb[likes[b] * Dn + t];
    xb[2 * Dn + t] = cate_emb[views[b] * Dn + t];
    xb[3 * Dn + t] = item_emb[(size_t)item_id[b] * Dn + t];
    xb[4 * Dn + t] = img;
    xb[5 * Dn + t] = hist;
}

// ---------------- K2: GAT + SE -> c[:, :768] (fp16) and s (fp32) -------------
__global__ __launch_bounds__(128) void k_gnn(
    const float* __restrict__ gnn_W, const float* __restrict__ gnn_a,
    const float* __restrict__ se_w1, const float* __restrict__ se_b1,
    const float* __restrict__ se_w2, const float* __restrict__ se_b2)
{
    int b = blockIdx.x, t = threadIdx.x;
    int h = t >> 5, lane = t & 31;
    __shared__ float xs[Fn * Dn];
    __shared__ float red[4 * Fn];

    const float* xb = g_x + (size_t)b * Fn * Dn;
    #pragma unroll
    for (int n = 0; n < Fn; n++) xs[n * Dn + t] = xb[n * Dn + t];
    __syncthreads();

    float hp[Fn];
    #pragma unroll
    for (int n = 0; n < Fn; n++) hp[n] = 0.f;
    const float* Wh = gnn_W + h * (Dn * 32) + lane;
    #pragma unroll
    for (int c = 0; c < 4; c++) {
        float w[32];
        #pragma unroll
        for (int q = 0; q < 32; q++) w[q] = Wh[(c * 32 + q) * 32];
        #pragma unroll
        for (int n = 0; n < Fn; n++) {
            const float4* xv = reinterpret_cast<const float4*>(&xs[n * Dn + c * 32]);
            float a = hp[n];
            #pragma unroll
            for (int q8 = 0; q8 < 8; q8++) {
                float4 v = xv[q8];
                a = fmaf(v.x, w[q8 * 4 + 0], a);
                a = fmaf(v.y, w[q8 * 4 + 1], a);
                a = fmaf(v.z, w[q8 * 4 + 2], a);
                a = fmaf(v.w, w[q8 * 4 + 3], a);
            }
            hp[n] = a;
        }
    }

    float a1 = gnn_a[h * 64 + lane];
    float a2 = gnn_a[h * 64 + 32 + lane];
    float ei[Fn], ej[Fn];
    #pragma unroll
    for (int n = 0; n < Fn; n++) {
        float v1 = hp[n] * a1, v2 = hp[n] * a2;
        #pragma unroll
        for (int o = 16; o; o >>= 1) {
            v1 += __shfl_xor_sync(0xffffffffu, v1, o);
            v2 += __shfl_xor_sync(0xffffffffu, v2, o);
        }
        ei[n] = v1; ej[n] = v2;
    }

    float gnn[Fn];
    #pragma unroll
    for (int n = 0; n < Fn; n++) {
        float em[Fn], mx = -1e30f;
        #pragma unroll
        for (int m = 0; m < Fn; m++) {
            float e = ei[n] + ej[m];
            e = e > 0.f ? e : 0.2f * e;
            em[m] = e; mx = fmaxf(mx, e);
        }
        float ss = 0.f;
        #pragma unroll
        for (int m = 0; m < Fn; m++) { em[m] = expf(em[m] - mx); ss += em[m]; }
        float inv = 1.f / ss, acc = 0.f;
        #pragma unroll
        for (int m = 0; m < Fn; m++) acc = fmaf(em[m], hp[m], acc);
        float hn = acc * inv + xs[n * Dn + t];
        gnn[n] = hn > 0.f ? hn : expm1f(hn);
    }

    #pragma unroll
    for (int n = 0; n < Fn; n++) {
        float v = gnn[n];
        #pragma unroll
        for (int o = 16; o; o >>= 1) v += __shfl_xor_sync(0xffffffffu, v, o);
        if (!lane) red[h * Fn + n] = v;
    }
    __syncthreads();

    float wv[Fn];
    {
        float z[Fn];
        #pragma unroll
        for (int n = 0; n < Fn; n++)
            z[n] = (red[0 * Fn + n] + red[1 * Fn + n] + red[2 * Fn + n] + red[3 * Fn + n]) * (1.f / Dn);
        float a[3];
        #pragma unroll
        for (int k = 0; k < 3; k++) {
            float v = se_b1[k];
            #pragma unroll
            for (int n = 0; n < Fn; n++) v = fmaf(z[n], se_w1[n * 3 + k], v);
            a[k] = fmaxf(v, 0.f);
        }
        #pragma unroll
        for (int f = 0; f < Fn; f++) {
            float v = se_b2[f];
            #pragma unroll
            for (int k = 0; k < 3; k++) v = fmaf(a[k], se_w2[k * 6 + f], v);
            wv[f] = 1.f / (1.f + expf(-v));
        }
    }

    __half* ch = g_c + (size_t)b * CINn;
    float* sb = g_s + (size_t)b * Fn * Dn;
    #pragma unroll
    for (int n = 0; n < Fn; n++) {
        float v = gnn[n];
        ch[n * Dn + t] = __float2half(v);
        sb[n * Dn + t] = v * wv[n];
    }
}

// ---------------- fp32 SGEMM for the bilinear (small) ------------------------
#define BMg 128
#define BNg 64
#define BKg 16
__global__ __launch_bounds__(256) void k_gemm(
    const float* __restrict__ A, int lda, long saz,
    const float* __restrict__ Wt, int ldb, long swz,
    float* __restrict__ Co, int ldc, long scz, int K)
{
    A  += (size_t)blockIdx.z * saz;
    Wt += (size_t)blockIdx.z * swz;
    Co += (size_t)blockIdx.z * scz;
    int bm = blockIdx.y * BMg, bn = blockIdx.x * BNg;
    int tid = threadIdx.x;
    int tx = tid & 15, ty = tid >> 4;

    __shared__ float As[BKg][BMg + 4];
    __shared__ float Bs[BKg][BNg + 4];

    float acc[8][4];
    #pragma unroll
    for (int i = 0; i < 8; i++)
        #pragma unroll
        for (int j = 0; j < 4; j++) acc[i][j] = 0.f;

    for (int k0 = 0; k0 < K; k0 += BKg) {
        #pragma unroll
        for (int ii = 0; ii < 2; ii++) {
            int e = tid + ii * 256;
            int m = e >> 2, k4 = (e & 3) * 4;
            const float4 v = *reinterpret_cast<const float4*>(&A[(size_t)(bm + m) * lda + k0 + k4]);
            As[k4 + 0][m] = v.x; As[k4 + 1][m] = v.y;
            As[k4 + 2][m] = v.z; As[k4 + 3][m] = v.w;
        }
        {
            int kk = tid >> 4, c4 = (tid & 15) * 4;
            const float4 v = *reinterpret_cast<const float4*>(&Wt[(size_t)(k0 + kk) * ldb + bn + c4]);
            Bs[kk][c4 + 0] = v.x; Bs[kk][c4 + 1] = v.y;
            Bs[kk][c4 + 2] = v.z; Bs[kk][c4 + 3] = v.w;
        }
        __syncthreads();
        #pragma unroll
        for (int kk = 0; kk < BKg; kk++) {
            float a[8], bb4[4];
            #pragma unroll
            for (int i = 0; i < 8; i++) a[i] = As[kk][ty * 8 + i];
            #pragma unroll
            for (int j = 0; j < 4; j++) bb4[j] = Bs[kk][tx * 4 + j];
            #pragma unroll
            for (int i = 0; i < 8; i++)
                #pragma unroll
                for (int j = 0; j < 4; j++) acc[i][j] = fmaf(a[i], bb4[j], acc[i][j]);
        }
        __syncthreads();
    }
    #pragma unroll
    for (int i = 0; i < 8; i++) {
        int row = bm + ty * 8 + i;
        #pragma unroll
        for (int j = 0; j < 4; j++)
            Co[(size_t)row * ldc + bn + tx * 4 + j] = acc[i][j];
    }
}

// ---------------- K4: bilinear pairs -> c[:, 768:] (fp16) --------------------
__global__ __launch_bounds__(128) void k_pairs()
{
    int b = blockIdx.x, t = threadIdx.x;
    const float* vid = g_vid + (size_t)b * (5 * Dn);
    const float* sb  = g_s   + (size_t)b * (Fn * Dn);
    __half* cp = g_c + (size_t)b * CINn + Fn * Dn;
    int p = 0;
    #pragma unroll
    for (int i = 0; i < 5; i++) {
        float vi = vid[i * Dn + t];
        #pragma unroll
        for (int j = i + 1; j < 6; j++) {
            cp[p * Dn + t] = __float2half(vi * sb[j * Dn + t]);
            p++;
        }
    }
}

// ---------------- weight transpose + fp16 hi/lo split ------------------------
__global__ __launch_bounds__(256) void k_wsplit(
    const float* __restrict__ W, __half* __restrict__ Th,
    __half* __restrict__ Tl, int K, int N)
{
    int idx = blockIdx.x * 256 + threadIdx.x;
    if (idx >= K * N) return;
    int k = idx / N, n = idx - k * N;
    float v = W[idx];
    __half hi = __float2half(v);
    Th[(size_t)n * K + k] = hi;
    Tl[(size_t)n * K + k] = __float2half(v - __half2float(hi));
}

// ---------------- fp16 weights-split GEMM via mma.sync + fused epilogue ------
// D[M,N] = A[M,K] @ (Bh+Bl)[N,K]^T ; A = fp16 single, B = fp16 hi/lo.
// 2 MMA terms per K-step. CTA 128x128, BK=32, 3-stage cp.async pipeline.
#define BM 128
#define BN 128
#define BK 32
#define ROWB 80u
#define OFF_A  0u
#define OFF_BH 10240u
#define OFF_BL 20480u
#define STAGEB 30720u
#define NSTAGE 3
#define SMEM_MMA (NSTAGE * STAGEB)

__global__ __launch_bounds__(256, 1) void k_mma(
    const __half* __restrict__ A,
    const __half* __restrict__ Bh, const __half* __restrict__ Bl,
    int K,
    float* __restrict__ outf, __half* __restrict__ oh, int ldc,
    const float* __restrict__ bias, const float* __restrict__ bng,
    const float* __restrict__ bnb, int mode)
{
    extern __shared__ char smem[];
    const uint32_t sbase = smem_u32(smem);
    const int tid = threadIdx.x;
    const int lane = tid & 31, wid = tid >> 5;
    const int wm = wid >> 2, wn = wid & 3;
    const int bm = blockIdx.y * BM, bn = blockIdx.x * BN;

    float acc[4][4][4];
    #pragma unroll
    for (int mi = 0; mi < 4; mi++)
        #pragma unroll
        for (int ni = 0; ni < 4; ni++)
            #pragma unroll
            for (int q = 0; q < 4; q++) acc[mi][ni][q] = 0.f;

    const uint32_t a_base = (uint32_t)(wm * 64 + (lane & 15)) * ROWB + (uint32_t)((lane >> 4) * 16);
    const uint32_t b_base = (uint32_t)(wn * 32 + (lane & 7) + ((lane >> 4) << 3)) * ROWB
                          + (uint32_t)(((lane >> 3) & 1) * 16);

    const int nIter = K / BK;

    auto load_stage = [&](int buf, int k0) {
        uint32_t base = sbase + (uint32_t)buf * STAGEB;
        #pragma unroll
        for (int half = 0; half < 2; half++) {
            int e = tid + half * 256;
            int r = e >> 2, c = e & 3;
            uint32_t off = (uint32_t)r * ROWB + (uint32_t)c * 16;
            size_t sa = (size_t)(bm + r) * K + k0 + c * 8;
            size_t sbv = (size_t)(bn + r) * K + k0 + c * 8;
            cp16(base + OFF_A  + off, A  + sa);
            cp16(base + OFF_BH + off, Bh + sbv);
            cp16(base + OFF_BL + off, Bl + sbv);
        }
    };

    load_stage(0, 0);
    cp_commit();
    if (nIter > 1) { load_stage(1, BK); cp_commit(); }

    int buf = 0;
    for (int it = 0; it < nIter; it++) {
        if (it + 2 < nIter) {
            load_stage((it + 2) % NSTAGE, (it + 2) * BK);
            cp_commit();
            cp_wait<2>();
        } else if (it + 1 < nIter) {
            cp_wait<1>();
        } else {
            cp_wait<0>();
        }
        __syncthreads();

        uint32_t base = sbase + (uint32_t)buf * STAGEB;
        #pragma unroll
        for (int ks = 0; ks < 2; ks++) {
            uint32_t koff = (uint32_t)ks * 32;
            uint32_t a[4][4], bh[2][4], bl[2][4];
            #pragma unroll
            for (int mi = 0; mi < 4; mi++) {
                uint32_t ao = a_base + (uint32_t)mi * 16 * ROWB + koff;
                ldsm4(a[mi], base + OFF_A + ao);
            }
            #pragma unroll
            for (int nq = 0; nq < 2; nq++) {
                uint32_t bo = b_base + (uint32_t)nq * 16 * ROWB + koff;
                ldsm4(bh[nq], base + OFF_BH + bo);
                ldsm4(bl[nq], base + OFF_BL + bo);
            }
            #pragma unroll
            for (int mi = 0; mi < 4; mi++) {
                #pragma unroll
                for (int ni = 0; ni < 4; ni++) {
                    const uint32_t* bhp = &bh[ni >> 1][(ni & 1) * 2];
                    const uint32_t* blp = &bl[ni >> 1][(ni & 1) * 2];
                    mma_fp16(acc[mi][ni], a[mi], bhp);
                    mma_fp16(acc[mi][ni], a[mi], blp);
                }
            }
        }
        __syncthreads();
        buf++; if (buf == NSTAGE) buf = 0;
    }

    const float bnscale = 0.999995000037499688f;  // 1/sqrt(1+1e-5)
    #pragma unroll
    for (int ni = 0; ni < 4; ni++) {
        int col = bn + wn * 32 + ni * 8 + (lane & 3) * 2;
        float bi0 = bias[col],     bi1 = bias[col + 1];
        float g0 = bng[col] * bnscale, g1 = bng[col + 1] * bnscale;
        float bb0 = bnb[col],      bb1 = bnb[col + 1];
        #pragma unroll
        for (int mi = 0; mi < 4; mi++) {
            int r0 = bm + wm * 64 + mi * 16 + (lane >> 2);
            #pragma unroll
            for (int half = 0; half < 2; half++) {
                int row = r0 + half * 8;
                float v0 = acc[mi][ni][half * 2 + 0];
                float v1 = acc[mi][ni][half * 2 + 1];
                v0 = (v0 + bi0) * g0 + bb0;
                v1 = (v1 + bi1) * g1 + bb1;
                v0 = 0.5f * v0 * (1.f + erff(v0 * 0.70710678118654752f));
                v1 = 0.5f * v1 * (1.f + erff(v1 * 0.70710678118654752f));
                if (mode == 2) {
                    outf[(size_t)row * ldc + col]     = v0;
                    outf[(size_t)row * ldc + col + 1] = v1;
                } else {
                    oh[(size_t)row * ldc + col]     = __float2half(v0);
                    oh[(size_t)row * ldc + col + 1] = __float2half(v1);
                }
            }
        }
    }
}

// ---------------- K5: final dot + sigmoid ------------------------------------
__global__ __launch_bounds__(256) void k_final(
    const float* __restrict__ w3, const float* __restrict__ b3,
    float* __restrict__ out)
{
    int warp = threadIdx.x >> 5, lane = threadIdx.x & 31;
    int b = blockIdx.x * 8 + warp;
    const float* hh = g_h2 + (size_t)b * H2N;
    float acc = 0.f;
    #pragma unroll
    for (int i = 0; i < 8; i++) acc = fmaf(hh[lane + i * 32], w3[lane + i * 32], acc);
    #pragma unroll
    for (int o = 16; o; o >>= 1) acc += __shfl_xor_sync(0xffffffffu, acc, o);
    if (!lane) out[b] = 1.f / (1.f + expf(-(acc + b3[0])));
}

// ---------------- launch -----------------------------------------------------
extern "C" void kernel_launch(void* const* d_in, const int* in_sizes, int n_in,
                              void* d_out, int out_size)
{
    const int*   item_id  = (const int*)  d_in[0];
    const float* item_mm  = (const float*)d_in[1];
    const int*   likes    = (const int*)  d_in[2];
    const int*   views    = (const int*)  d_in[3];
    const int*   item_seq = (const int*)  d_in[4];
    const float* item_emb = (const float*)d_in[5];
    const float* cate_emb = (const float*)d_in[6];
    const float* mm_w     = (const float*)d_in[7];
    const float* mm_b     = (const float*)d_in[8];
    const float* ln_g     = (const float*)d_in[9];
    const float* ln_b     = (const float*)d_in[10];
    const float* gnn_W    = (const float*)d_in[11];
    const float* gnn_a    = (const float*)d_in[12];
    const float* se_w1    = (const float*)d_in[13];
    const float* se_b1    = (const float*)d_in[14];
    const float* se_w2    = (const float*)d_in[15];
    const float* se_b2    = (const float*)d_in[16];
    const float* bi_W     = (const float*)d_in[17];
    const float* w1       = (const float*)d_in[18];
    const float* b1       = (const float*)d_in[19];
    const float* bn1g     = (const float*)d_in[20];
    const float* bn1b     = (const float*)d_in[21];
    const float* w2       = (const float*)d_in[22];
    const float* b2       = (const float*)d_in[23];
    const float* bn2g     = (const float*)d_in[24];
    const float* bn2b     = (const float*)d_in[25];
    const float* w3       = (const float*)d_in[26];
    const float* b3       = (const float*)d_in[27];
    float* out = (float*)d_out;

    float *ps, *pv, *ph2;
    __half *pc, *ph1, *pw1h, *pw1l, *pw2h, *pw2l;
    cudaGetSymbolAddress((void**)&ps,   g_s);
    cudaGetSymbolAddress((void**)&pv,   g_vid);
    cudaGetSymbolAddress((void**)&ph2,  g_h2);
    cudaGetSymbolAddress((void**)&pc,   g_c);
    cudaGetSymbolAddress((void**)&ph1,  g_h1);
    cudaGetSymbolAddress((void**)&pw1h, g_w1t_hi);
    cudaGetSymbolAddress((void**)&pw1l, g_w1t_lo);
    cudaGetSymbolAddress((void**)&pw2h, g_w2t_hi);
    cudaGetSymbolAddress((void**)&pw2l, g_w2t_lo);

    cudaFuncSetAttribute(k_mma, cudaFuncAttributeMaxDynamicSharedMemorySize, SMEM_MMA);

    // weight prep (fp16 hi/lo split + transpose)
    k_wsplit<<<(CINn * H1N + 255) / 256, 256>>>(w1, pw1h, pw1l, CINn, H1N);
    k_wsplit<<<(H1N * H2N + 255) / 256, 256>>>(w2, pw2h, pw2l, H1N, H2N);

    k_features<<<Bn, 128>>>(item_id, item_mm, likes, views, item_seq,
                            item_emb, cate_emb, mm_w, mm_b, ln_g, ln_b);
    k_gnn<<<Bn, 128>>>(gnn_W, gnn_a, se_w1, se_b1, se_w2, se_b2);

    // bilinear: vid[b,f,:] = s[b,f,:] @ bi_W[f]
    {
        dim3 grid(Dn / BNg, Bn / BMg, 5);
        k_gemm<<<grid, 256>>>(ps, Fn * Dn, Dn, bi_W, Dn, (long)Dn * Dn,
                              pv, 5 * Dn, Dn, Dn);
    }
    k_pairs<<<Bn, 128>>>();

    // layer 1: c @ w1 (+bias,bn,gelu) -> h1 (fp16)
    {
        dim3 grid(H1N / BN, Bn / BM);
        k_mma<<<grid, 256, SMEM_MMA>>>(pc, pw1h, pw1l, CINn,
                                       nullptr, ph1, H1N, b1, bn1g, bn1b, 1);
    }
    // layer 2: h1 @ w2 (+bias,bn,gelu) -> h2 (fp32)
    {
        dim3 grid(H2N / BN, Bn / BM);
        k_mma<<<grid, 256, SMEM_MMA>>>(ph1, pw2h, pw2l, H1N,
                                       ph2, nullptr, H2N, b2, bn2g, bn2b, 2);
    }
    k_final<<<Bn / 8, 256>>>(w3, b3, out);
}

// round 8
// speedup vs baseline: 2.1730x; 1.2933x over previous
#include <cuda_runtime.h>
#include <cuda_fp16.h>
#include <math.h>
#include <stdint.h>

#define Bn 16384
#define Ln 50
#define Dn 128
#define Fn 6
#define CINn 2688
#define H1N 512
#define H2N 256

// ---------------- scratch (static device globals) ---------------------------
__device__ __align__(16) float g_x  [Bn * Fn * Dn];
__device__ __align__(16) __half g_s  [Bn * Fn * Dn];   // fp16 SE-scaled feats
__device__ __align__(16) __half g_vid[Bn * 5 * Dn];    // fp16 bilinear out
__device__ __align__(16) __half g_c  [Bn * CINn];      // fp16 activations
__device__ __align__(16) __half g_h1 [Bn * H1N];
__device__ __align__(16) float g_h2 [Bn * H2N];
__device__ __align__(16) __half g_w1t[H1N * CINn];     // fp16 weights (transposed)
__device__ __align__(16) __half g_w2t[H2N * H1N];
__device__ __align__(16) __half g_wb [5 * Dn * Dn];    // bi_W as [f][e][d]

// ---------------- PTX helpers (sm_80-level only) -----------------------------
__device__ __forceinline__ uint32_t smem_u32(const void* p) {
    uint32_t a;
    asm("{ .reg .u64 t; cvta.to.shared.u64 t, %1; cvt.u32.u64 %0, t; }" : "=r"(a) : "l"(p));
    return a;
}
__device__ __forceinline__ void cp16(uint32_t dst, const void* src) {
    asm volatile("cp.async.cg.shared.global [%0], [%1], 16;" :: "r"(dst), "l"(src));
}
__device__ __forceinline__ void cp_commit() {
    asm volatile("cp.async.commit_group;" ::: "memory");
}
template <int N>
__device__ __forceinline__ void cp_wait() {
    asm volatile("cp.async.wait_group %0;" :: "n"(N) : "memory");
}
__device__ __forceinline__ void ldsm4(uint32_t* r, uint32_t addr) {
    asm volatile("ldmatrix.sync.aligned.m8n8.x4.shared.b16 {%0,%1,%2,%3}, [%4];"
                 : "=r"(r[0]), "=r"(r[1]), "=r"(r[2]), "=r"(r[3]) : "r"(addr));
}
__device__ __forceinline__ void mma_fp16(float* d, const uint32_t* a, const uint32_t* b) {
    asm volatile(
        "mma.sync.aligned.m16n8k16.row.col.f32.f16.f16.f32 "
        "{%0,%1,%2,%3}, {%4,%5,%6,%7}, {%8,%9}, {%0,%1,%2,%3};"
        : "+f"(d[0]), "+f"(d[1]), "+f"(d[2]), "+f"(d[3])
        : "r"(a[0]), "r"(a[1]), "r"(a[2]), "r"(a[3]), "r"(b[0]), "r"(b[1]));
}

// ---------------- K1: features -> x[b, 6, 128] ------------------------------
__global__ __launch_bounds__(128) void k_features(
    const int* __restrict__ item_id, const float* __restrict__ item_mm,
    const int* __restrict__ likes, const int* __restrict__ views,
    const int* __restrict__ item_seq, const float* __restrict__ item_emb,
    const float* __restrict__ cate_emb, const float* __restrict__ mm_w,
    const float* __restrict__ mm_b, const float* __restrict__ ln_g,
    const float* __restrict__ ln_b)
{
    int b = blockIdx.x, t = threadIdx.x;
    int lane = t & 31, w = t >> 5;
    __shared__ float sm[Dn];
    __shared__ float red[8];

    sm[t] = item_mm[b * Dn + t];
    __syncthreads();

    float y = mm_b[t];
    #pragma unroll 16
    for (int i = 0; i < Dn; i++) y = fmaf(sm[i], mm_w[i * Dn + t], y);

    float s1 = y, s2 = y * y;
    #pragma unroll
    for (int o = 16; o; o >>= 1) {
        s1 += __shfl_xor_sync(0xffffffffu, s1, o);
        s2 += __shfl_xor_sync(0xffffffffu, s2, o);
    }
    if (!lane) { red[w] = s1; red[4 + w] = s2; }
    __syncthreads();
    float mu = (red[0] + red[1] + red[2] + red[3]) * (1.f / Dn);
    float m2 = (red[4] + red[5] + red[6] + red[7]) * (1.f / Dn);
    float var = m2 - mu * mu;
    float yn = (y - mu) * rsqrtf(var + 1e-5f) * ln_g[t] + ln_b[t];
    float img = 0.5f * yn * (1.f + erff(yn * 0.70710678118654752f));

    float hs = 0.f, cnt = 0.f;
    const int* seq = item_seq + b * Ln;
    for (int l = 0; l < Ln; l++) {
        int id = seq[l];
        if (id != 0) { hs += item_emb[(size_t)id * Dn + t]; cnt += 1.f; }
    }
    float hist = hs / fmaxf(cnt, 1.f);

    float* xb = g_x + (size_t)b * (Fn * Dn);
    xb[0 * Dn + t] = 0.f;
    xb[1 * Dn + t] = cate_emb[likes[b] * Dn + t];
    xb[2 * Dn + t] = cate_emb[views[b] * Dn + t];
    xb[3 * Dn + t] = item_emb[(size_t)item_id[b] * Dn + t];
    xb[4 * Dn + t] = img;
    xb[5 * Dn + t] = hist;
}

// ---------------- K2: GAT + SE -> c[:, :768] (fp16), s (fp16) ----------------
__global__ __launch_bounds__(128) void k_gnn(
    const float* __restrict__ gnn_W, const float* __restrict__ gnn_a,
    const float* __restrict__ se_w1, const float* __restrict__ se_b1,
    const float* __restrict__ se_w2, const float* __restrict__ se_b2)
{
    int b = blockIdx.x, t = threadIdx.x;
    int h = t >> 5, lane = t & 31;
    __shared__ float xs[Fn * Dn];
    __shared__ float red[4 * Fn];

    const float* xb = g_x + (size_t)b * Fn * Dn;
    #pragma unroll
    for (int n = 0; n < Fn; n++) xs[n * Dn + t] = xb[n * Dn + t];
    __syncthreads();

    float hp[Fn];
    #pragma unroll
    for (int n = 0; n < Fn; n++) hp[n] = 0.f;
    const float* Wh = gnn_W + h * (Dn * 32) + lane;
    #pragma unroll
    for (int c = 0; c < 4; c++) {
        float w[32];
        #pragma unroll
        for (int q = 0; q < 32; q++) w[q] = Wh[(c * 32 + q) * 32];
        #pragma unroll
        for (int n = 0; n < Fn; n++) {
            const float4* xv = reinterpret_cast<const float4*>(&xs[n * Dn + c * 32]);
            float a = hp[n];
            #pragma unroll
            for (int q8 = 0; q8 < 8; q8++) {
                float4 v = xv[q8];
                a = fmaf(v.x, w[q8 * 4 + 0], a);
                a = fmaf(v.y, w[q8 * 4 + 1], a);
                a = fmaf(v.z, w[q8 * 4 + 2], a);
                a = fmaf(v.w, w[q8 * 4 + 3], a);
            }
            hp[n] = a;
        }
    }

    float a1 = gnn_a[h * 64 + lane];
    float a2 = gnn_a[h * 64 + 32 + lane];
    float ei[Fn], ej[Fn];
    #pragma unroll
    for (int n = 0; n < Fn; n++) {
        float v1 = hp[n] * a1, v2 = hp[n] * a2;
        #pragma unroll
        for (int o = 16; o; o >>= 1) {
            v1 += __shfl_xor_sync(0xffffffffu, v1, o);
            v2 += __shfl_xor_sync(0xffffffffu, v2, o);
        }
        ei[n] = v1; ej[n] = v2;
    }

    float gnn[Fn];
    #pragma unroll
    for (int n = 0; n < Fn; n++) {
        float em[Fn], mx = -1e30f;
        #pragma unroll
        for (int m = 0; m < Fn; m++) {
            float e = ei[n] + ej[m];
            e = e > 0.f ? e : 0.2f * e;
            em[m] = e; mx = fmaxf(mx, e);
        }
        float ss = 0.f;
        #pragma unroll
        for (int m = 0; m < Fn; m++) { em[m] = expf(em[m] - mx); ss += em[m]; }
        float inv = 1.f / ss, acc = 0.f;
        #pragma unroll
        for (int m = 0; m < Fn; m++) acc = fmaf(em[m], hp[m], acc);
        float hn = acc * inv + xs[n * Dn + t];
        gnn[n] = hn > 0.f ? hn : expm1f(hn);
    }

    #pragma unroll
    for (int n = 0; n < Fn; n++) {
        float v = gnn[n];
        #pragma unroll
        for (int o = 16; o; o >>= 1) v += __shfl_xor_sync(0xffffffffu, v, o);
        if (!lane) red[h * Fn + n] = v;
    }
    __syncthreads();

    float wv[Fn];
    {
        float z[Fn];
        #pragma unroll
        for (int n = 0; n < Fn; n++)
            z[n] = (red[0 * Fn + n] + red[1 * Fn + n] + red[2 * Fn + n] + red[3 * Fn + n]) * (1.f / Dn);
        float a[3];
        #pragma unroll
        for (int k = 0; k < 3; k++) {
            float v = se_b1[k];
            #pragma unroll
            for (int n = 0; n < Fn; n++) v = fmaf(z[n], se_w1[n * 3 + k], v);
            a[k] = fmaxf(v, 0.f);
        }
        #pragma unroll
        for (int f = 0; f < Fn; f++) {
            float v = se_b2[f];
            #pragma unroll
            for (int k = 0; k < 3; k++) v = fmaf(a[k], se_w2[k * 6 + f], v);
            wv[f] = 1.f / (1.f + expf(-v));
        }
    }

    __half* ch = g_c + (size_t)b * CINn;
    __half* sb = g_s + (size_t)b * Fn * Dn;
    #pragma unroll
    for (int n = 0; n < Fn; n++) {
        float v = gnn[n];
        ch[n * Dn + t] = __float2half(v);
        sb[n * Dn + t] = __float2half(v * wv[n]);
    }
}

// ---------------- K4: bilinear pairs -> c[:, 768:] (fp16) --------------------
__global__ __launch_bounds__(128) void k_pairs()
{
    int b = blockIdx.x, t = threadIdx.x;
    const __half* vid = g_vid + (size_t)b * (5 * Dn);
    const __half* sb  = g_s   + (size_t)b * (Fn * Dn);
    __half* cp = g_c + (size_t)b * CINn + Fn * Dn;
    float sv[Fn];
    #pragma unroll
    for (int j = 0; j < Fn; j++) sv[j] = __half2float(sb[j * Dn + t]);
    int p = 0;
    #pragma unroll
    for (int i = 0; i < 5; i++) {
        float vi = __half2float(vid[i * Dn + t]);
        #pragma unroll
        for (int j = i + 1; j < 6; j++) {
            cp[p * Dn + t] = __float2half(vi * sv[j]);
            p++;
        }
    }
}

// ---------------- weight prep: transpose + fp16 ------------------------------
__global__ __launch_bounds__(256) void k_wt(
    const float* __restrict__ W, __half* __restrict__ T, int K, int N)
{
    int idx = blockIdx.x * 256 + threadIdx.x;
    if (idx >= K * N) return;
    int k = idx / N, n = idx - k * N;
    T[(size_t)n * K + k] = __float2half(W[idx]);
}
// bi_W[f][d][e] -> [f][n=e][k=d], fp16
__global__ __launch_bounds__(256) void k_wbi(const float* __restrict__ W)
{
    int idx = blockIdx.x * 256 + threadIdx.x;
    if (idx >= 5 * 128 * 128) return;
    int f = idx >> 14, rem = idx & 16383;
    int d = rem >> 7, e = rem & 127;
    g_wb[(f << 14) + e * 128 + d] = __float2half(W[idx]);
}

// ---------------- fp16 GEMM via mma.sync + fused epilogue --------------------
// D[M,N] = A[M,K] @ B[N,K]^T, both fp16 single. z-batched via az/bz/cz (elems).
// modes: 1 = bias+bn+gelu -> fp16; 2 = bias+bn+gelu -> fp32; 3 = raw -> fp16.
#define BM 128
#define BN 128
#define BK 32
#define ROWB 80u
#define OFF_A  0u
#define OFF_B  10240u
#define STAGEB 20480u
#define NSTAGE 4
#define SMEM_MMA (NSTAGE * STAGEB)

__global__ __launch_bounds__(256, 1) void k_mma(
    const __half* __restrict__ A, const __half* __restrict__ B,
    int K, int lda, long az, long bz, long cz,
    float* __restrict__ outf, __half* __restrict__ oh, int ldc,
    const float* __restrict__ bias, const float* __restrict__ bng,
    const float* __restrict__ bnb, int mode)
{
    extern __shared__ char smem[];
    const uint32_t sbase = smem_u32(smem);
    const int tid = threadIdx.x;
    const int lane = tid & 31, wid = tid >> 5;
    const int wm = wid >> 2, wn = wid & 3;
    const int bm = blockIdx.y * BM, bn = blockIdx.x * BN;
    const int z = blockIdx.z;
    A += (size_t)z * az;
    B += (size_t)z * bz;

    float acc[4][4][4];
    #pragma unroll
    for (int mi = 0; mi < 4; mi++)
        #pragma unroll
        for (int ni = 0; ni < 4; ni++)
            #pragma unroll
            for (int q = 0; q < 4; q++) acc[mi][ni][q] = 0.f;

    const uint32_t a_base = (uint32_t)(wm * 64 + (lane & 15)) * ROWB + (uint32_t)((lane >> 4) * 16);
    const uint32_t b_base = (uint32_t)(wn * 32 + (lane & 7) + ((lane >> 4) << 3)) * ROWB
                          + (uint32_t)(((lane >> 3) & 1) * 16);

    const int nIter = K / BK;

    auto load_stage = [&](int buf, int k0) {
        uint32_t base = sbase + (uint32_t)buf * STAGEB;
        #pragma unroll
        for (int half = 0; half < 2; half++) {
            int e = tid + half * 256;
            int r = e >> 2, c = e & 3;
            uint32_t off = (uint32_t)r * ROWB + (uint32_t)c * 16;
            cp16(base + OFF_A + off, A + (size_t)(bm + r) * lda + k0 + c * 8);
            cp16(base + OFF_B + off, B + (size_t)(bn + r) * K   + k0 + c * 8);
        }
    };

    load_stage(0, 0);
    cp_commit();
    load_stage(1, BK);
    cp_commit();
    load_stage(2, 2 * BK);
    cp_commit();

    for (int it = 0; it < nIter; it++) {
        if (it + 3 < nIter) {
            load_stage((it + 3) & 3, (it + 3) * BK);
            cp_commit();
            cp_wait<3>();
        } else if (it + 2 < nIter) {
            cp_wait<2>();
        } else if (it + 1 < nIter) {
            cp_wait<1>();
        } else {
            cp_wait<0>();
        }
        __syncthreads();

        uint32_t base = sbase + (uint32_t)(it & 3) * STAGEB;
        #pragma unroll
        for (int ks = 0; ks < 2; ks++) {
            uint32_t koff = (uint32_t)ks * 32;
            uint32_t a[4][4], bb[2][4];
            #pragma unroll
            for (int mi = 0; mi < 4; mi++)
                ldsm4(a[mi], base + OFF_A + a_base + (uint32_t)mi * 16 * ROWB + koff);
            #pragma unroll
            for (int nq = 0; nq < 2; nq++)
                ldsm4(bb[nq], base + OFF_B + b_base + (uint32_t)nq * 16 * ROWB + koff);
            #pragma unroll
            for (int mi = 0; mi < 4; mi++)
                #pragma unroll
                for (int ni = 0; ni < 4; ni++)
                    mma_fp16(acc[mi][ni], a[mi], &bb[ni >> 1][(ni & 1) * 2]);
        }
        __syncthreads();
    }

    const float bnscale = 0.999995000037499688f;  // 1/sqrt(1+1e-5)
    #pragma unroll
    for (int ni = 0; ni < 4; ni++) {
        int col = bn + wn * 32 + ni * 8 + (lane & 3) * 2;
        float bi0 = 0.f, bi1 = 0.f, g0 = 1.f, g1 = 1.f, bb0 = 0.f, bb1 = 0.f;
        if (mode != 3) {
            bi0 = bias[col];             bi1 = bias[col + 1];
            g0 = bng[col] * bnscale;     g1 = bng[col + 1] * bnscale;
            bb0 = bnb[col];              bb1 = bnb[col + 1];
        }
        #pragma unroll
        for (int mi = 0; mi < 4; mi++) {
            int r0 = bm + wm * 64 + mi * 16 + (lane >> 2);
            #pragma unroll
            for (int half = 0; half < 2; half++) {
                int row = r0 + half * 8;
                float v0 = acc[mi][ni][half * 2 + 0];
                float v1 = acc[mi][ni][half * 2 + 1];
                if (mode == 3) {
                    __half* od = oh + (size_t)z * cz;
                    od[(size_t)row * ldc + col]     = __float2half(v0);
                    od[(size_t)row * ldc + col + 1] = __float2half(v1);
                    continue;
                }
                v0 = (v0 + bi0) * g0 + bb0;
                v1 = (v1 + bi1) * g1 + bb1;
                v0 = 0.5f * v0 * (1.f + erff(v0 * 0.70710678118654752f));
                v1 = 0.5f * v1 * (1.f + erff(v1 * 0.70710678118654752f));
                if (mode == 2) {
                    outf[(size_t)row * ldc + col]     = v0;
                    outf[(size_t)row * ldc + col + 1] = v1;
                } else {
                    oh[(size_t)row * ldc + col]     = __float2half(v0);
                    oh[(size_t)row * ldc + col + 1] = __float2half(v1);
                }
            }
        }
    }
}

// ---------------- K5: final dot + sigmoid ------------------------------------
__global__ __launch_bounds__(256) void k_final(
    const float* __restrict__ w3, const float* __restrict__ b3,
    float* __restrict__ out)
{
    int warp = threadIdx.x >> 5, lane = threadIdx.x & 31;
    int b = blockIdx.x * 8 + warp;
    const float* hh = g_h2 + (size_t)b * H2N;
    float acc = 0.f;
    #pragma unroll
    for (int i = 0; i < 8; i++) acc = fmaf(hh[lane + i * 32], w3[lane + i * 32], acc);
    #pragma unroll
    for (int o = 16; o; o >>= 1) acc += __shfl_xor_sync(0xffffffffu, acc, o);
    if (!lane) out[b] = 1.f / (1.f + expf(-(acc + b3[0])));
}

// ---------------- launch -----------------------------------------------------
extern "C" void kernel_launch(void* const* d_in, const int* in_sizes, int n_in,
                              void* d_out, int out_size)
{
    const int*   item_id  = (const int*)  d_in[0];
    const float* item_mm  = (const float*)d_in[1];
    const int*   likes    = (const int*)  d_in[2];
    const int*   views    = (const int*)  d_in[3];
    const int*   item_seq = (const int*)  d_in[4];
    const float* item_emb = (const float*)d_in[5];
    const float* cate_emb = (const float*)d_in[6];
    const float* mm_w     = (const float*)d_in[7];
    const float* mm_b     = (const float*)d_in[8];
    const float* ln_g     = (const float*)d_in[9];
    const float* ln_b     = (const float*)d_in[10];
    const float* gnn_W    = (const float*)d_in[11];
    const float* gnn_a    = (const float*)d_in[12];
    const float* se_w1    = (const float*)d_in[13];
    const float* se_b1    = (const float*)d_in[14];
    const float* se_w2    = (const float*)d_in[15];
    const float* se_b2    = (const float*)d_in[16];
    const float* bi_W     = (const float*)d_in[17];
    const float* w1       = (const float*)d_in[18];
    const float* b1       = (const float*)d_in[19];
    const float* bn1g     = (const float*)d_in[20];
    const float* bn1b     = (const float*)d_in[21];
    const float* w2       = (const float*)d_in[22];
    const float* b2       = (const float*)d_in[23];
    const float* bn2g     = (const float*)d_in[24];
    const float* bn2b     = (const float*)d_in[25];
    const float* w3       = (const float*)d_in[26];
    const float* b3       = (const float*)d_in[27];
    float* out = (float*)d_out;

    float *ph2;
    __half *ps, *pvid, *pc, *ph1, *pw1, *pw2, *pwb;
    cudaGetSymbolAddress((void**)&ps,   g_s);
    cudaGetSymbolAddress((void**)&pvid, g_vid);
    cudaGetSymbolAddress((void**)&ph2,  g_h2);
    cudaGetSymbolAddress((void**)&pc,   g_c);
    cudaGetSymbolAddress((void**)&ph1,  g_h1);
    cudaGetSymbolAddress((void**)&pw1,  g_w1t);
    cudaGetSymbolAddress((void**)&pw2,  g_w2t);
    cudaGetSymbolAddress((void**)&pwb,  g_wb);

    cudaFuncSetAttribute(k_mma, cudaFuncAttributeMaxDynamicSharedMemorySize, SMEM_MMA);

    // weight prep (fp16 transpose)
    k_wt<<<(CINn * H1N + 255) / 256, 256>>>(w1, pw1, CINn, H1N);
    k_wt<<<(H1N * H2N + 255) / 256, 256>>>(w2, pw2, H1N, H2N);
    k_wbi<<<(5 * 128 * 128 + 255) / 256, 256>>>(bi_W);

    k_features<<<Bn, 128>>>(item_id, item_mm, likes, views, item_seq,
                            item_emb, cate_emb, mm_w, mm_b, ln_g, ln_b);
    k_gnn<<<Bn, 128>>>(gnn_W, gnn_a, se_w1, se_b1, se_w2, se_b2);

    // bilinear: vid[b,f,:] = s[b,f,:] @ bi_W[f]^T  (fp16 HMMA, z = field)
    {
        dim3 grid(1, Bn / BM, 5);
        k_mma<<<grid, 256, SMEM_MMA>>>(ps, pwb, Dn, Fn * Dn,
                                       Dn, (long)Dn * Dn, Dn,
                                       nullptr, pvid, 5 * Dn,
                                       nullptr, nullptr, nullptr, 3);
    }
    k_pairs<<<Bn, 128>>>();

    // layer 1: c @ w1 (+bias,bn,gelu) -> h1 (fp16)
    {
        dim3 grid(H1N / BN, Bn / BM, 1);
        k_mma<<<grid, 256, SMEM_MMA>>>(pc, pw1, CINn, CINn, 0, 0, 0,
                                       nullptr, ph1, H1N, b1, bn1g, bn1b, 1);
    }
    // layer 2: h1 @ w2 (+bias,bn,gelu) -> h2 (fp32)
    {
        dim3 grid(H2N / BN, Bn / BM, 1);
        k_mma<<<grid, 256, SMEM_MMA>>>(ph1, pw2, H1N, H1N, 0, 0, 0,
                                       ph2, nullptr, H2N, b2, bn2g, bn2b, 2);
    }
    k_final<<<Bn / 8, 256>>>(w3, b3, out);
}

// round 9
// speedup vs baseline: 2.2132x; 1.0185x over previous
#include <cuda_runtime.h>
#include <cuda_fp16.h>
#include <math.h>
#include <stdint.h>

#define Bn 16384
#define Ln 50
#define Dn 128
#define Fn 6
#define CINn 2688
#define H1N 512
#define H2N 256

// ---------------- scratch (static device globals) ---------------------------
__device__ __align__(16) float g_x  [Bn * Fn * Dn];
__device__ __align__(16) __half g_s  [Bn * Fn * Dn];   // fp16 SE-scaled feats
__device__ __align__(16) __half g_c  [Bn * CINn];      // fp16 activations
__device__ __align__(16) __half g_h1 [Bn * H1N];
__device__ __align__(16) float g_h2 [Bn * H2N];
__device__ __align__(16) __half g_w1t[H1N * CINn];     // fp16 weights (transposed)
__device__ __align__(16) __half g_w2t[H2N * H1N];
__device__ __align__(16) __half g_wb [5 * Dn * Dn];    // bi_W as [f][e][d]

// ---------------- PTX helpers (sm_80-level only) -----------------------------
__device__ __forceinline__ uint32_t smem_u32(const void* p) {
    uint32_t a;
    asm("{ .reg .u64 t; cvta.to.shared.u64 t, %1; cvt.u32.u64 %0, t; }" : "=r"(a) : "l"(p));
    return a;
}
__device__ __forceinline__ void cp16(uint32_t dst, const void* src) {
    asm volatile("cp.async.cg.shared.global [%0], [%1], 16;" :: "r"(dst), "l"(src));
}
__device__ __forceinline__ void cp_commit() {
    asm volatile("cp.async.commit_group;" ::: "memory");
}
template <int N>
__device__ __forceinline__ void cp_wait() {
    asm volatile("cp.async.wait_group %0;" :: "n"(N) : "memory");
}
__device__ __forceinline__ void ldsm4(uint32_t* r, uint32_t addr) {
    asm volatile("ldmatrix.sync.aligned.m8n8.x4.shared.b16 {%0,%1,%2,%3}, [%4];"
                 : "=r"(r[0]), "=r"(r[1]), "=r"(r[2]), "=r"(r[3]) : "r"(addr));
}
__device__ __forceinline__ void mma_fp16(float* d, const uint32_t* a, const uint32_t* b) {
    asm volatile(
        "mma.sync.aligned.m16n8k16.row.col.f32.f16.f16.f32 "
        "{%0,%1,%2,%3}, {%4,%5,%6,%7}, {%8,%9}, {%0,%1,%2,%3};"
        : "+f"(d[0]), "+f"(d[1]), "+f"(d[2]), "+f"(d[3])
        : "r"(a[0]), "r"(a[1]), "r"(a[2]), "r"(a[3]), "r"(b[0]), "r"(b[1]));
}

// ---------------- K1: features -> x[b, 6, 128] ------------------------------
__global__ __launch_bounds__(128) void k_features(
    const int* __restrict__ item_id, const float* __restrict__ item_mm,
    const int* __restrict__ likes, const int* __restrict__ views,
    const int* __restrict__ item_seq, const float* __restrict__ item_emb,
    const float* __restrict__ cate_emb, const float* __restrict__ mm_w,
    const float* __restrict__ mm_b, const float* __restrict__ ln_g,
    const float* __restrict__ ln_b)
{
    int b = blockIdx.x, t = threadIdx.x;
    int lane = t & 31, w = t >> 5;
    __shared__ float sm[Dn];
    __shared__ float red[8];
    __shared__ int sseq[Ln];

    sm[t] = item_mm[b * Dn + t];
    if (t < Ln) sseq[t] = item_seq[b * Ln + t];
    __syncthreads();

    // y = item_mm @ mm_w + b, with mm_w chunk-hoisted to registers
    float y = mm_b[t];
    const float* Wc = mm_w + t;
    #pragma unroll
    for (int c = 0; c < 4; c++) {
        float wv[32];
        #pragma unroll
        for (int q = 0; q < 32; q++) wv[q] = Wc[(c * 32 + q) * Dn];
        const float4* xv = reinterpret_cast<const float4*>(&sm[c * 32]);
        #pragma unroll
        for (int q8 = 0; q8 < 8; q8++) {
            float4 v = xv[q8];
            y = fmaf(v.x, wv[q8 * 4 + 0], y);
            y = fmaf(v.y, wv[q8 * 4 + 1], y);
            y = fmaf(v.z, wv[q8 * 4 + 2], y);
            y = fmaf(v.w, wv[q8 * 4 + 3], y);
        }
    }

    float s1 = y, s2 = y * y;
    #pragma unroll
    for (int o = 16; o; o >>= 1) {
        s1 += __shfl_xor_sync(0xffffffffu, s1, o);
        s2 += __shfl_xor_sync(0xffffffffu, s2, o);
    }
    if (!lane) { red[w] = s1; red[4 + w] = s2; }
    __syncthreads();
    float mu = (red[0] + red[1] + red[2] + red[3]) * (1.f / Dn);
    float m2 = (red[4] + red[5] + red[6] + red[7]) * (1.f / Dn);
    float var = m2 - mu * mu;
    float yn = (y - mu) * rsqrtf(var + 1e-5f) * ln_g[t] + ln_b[t];
    float img = 0.5f * yn * (1.f + erff(yn * 0.70710678118654752f));

    // branch-free masked mean: item_emb[0] == 0 by construction
    float hs = 0.f;
    int cnt = 0;
    #pragma unroll 10
    for (int l = 0; l < Ln; l++) {
        int id = sseq[l];
        hs += item_emb[(size_t)id * Dn + t];
        cnt += (id != 0);
    }
    float hist = hs / fmaxf((float)cnt, 1.f);

    float* xb = g_x + (size_t)b * (Fn * Dn);
    xb[0 * Dn + t] = 0.f;
    xb[1 * Dn + t] = cate_emb[likes[b] * Dn + t];
    xb[2 * Dn + t] = cate_emb[views[b] * Dn + t];
    xb[3 * Dn + t] = item_emb[(size_t)item_id[b] * Dn + t];
    xb[4 * Dn + t] = img;
    xb[5 * Dn + t] = hist;
}

// ---------------- K2: GAT + SE -> c[:, :768] (fp16), s (fp16) ----------------
__global__ __launch_bounds__(128) void k_gnn(
    const float* __restrict__ gnn_W, const float* __restrict__ gnn_a,
    const float* __restrict__ se_w1, const float* __restrict__ se_b1,
    const float* __restrict__ se_w2, const float* __restrict__ se_b2)
{
    int b = blockIdx.x, t = threadIdx.x;
    int h = t >> 5, lane = t & 31;
    __shared__ float xs[Fn * Dn];
    __shared__ float red[4 * Fn];

    const float* xb = g_x + (size_t)b * Fn * Dn;
    #pragma unroll
    for (int n = 0; n < Fn; n++) xs[n * Dn + t] = xb[n * Dn + t];
    __syncthreads();

    float hp[Fn];
    #pragma unroll
    for (int n = 0; n < Fn; n++) hp[n] = 0.f;
    const float* Wh = gnn_W + h * (Dn * 32) + lane;
    #pragma unroll
    for (int c = 0; c < 4; c++) {
        float w[32];
        #pragma unroll
        for (int q = 0; q < 32; q++) w[q] = Wh[(c * 32 + q) * 32];
        #pragma unroll
        for (int n = 0; n < Fn; n++) {
            const float4* xv = reinterpret_cast<const float4*>(&xs[n * Dn + c * 32]);
            float a = hp[n];
            #pragma unroll
            for (int q8 = 0; q8 < 8; q8++) {
                float4 v = xv[q8];
                a = fmaf(v.x, w[q8 * 4 + 0], a);
                a = fmaf(v.y, w[q8 * 4 + 1], a);
                a = fmaf(v.z, w[q8 * 4 + 2], a);
                a = fmaf(v.w, w[q8 * 4 + 3], a);
            }
            hp[n] = a;
        }
    }

    float a1 = gnn_a[h * 64 + lane];
    float a2 = gnn_a[h * 64 + 32 + lane];
    float ei[Fn], ej[Fn];
    #pragma unroll
    for (int n = 0; n < Fn; n++) {
        float v1 = hp[n] * a1, v2 = hp[n] * a2;
        #pragma unroll
        for (int o = 16; o; o >>= 1) {
            v1 += __shfl_xor_sync(0xffffffffu, v1, o);
            v2 += __shfl_xor_sync(0xffffffffu, v2, o);
        }
        ei[n] = v1; ej[n] = v2;
    }

    float gnn[Fn];
    #pragma unroll
    for (int n = 0; n < Fn; n++) {
        float em[Fn], mx = -1e30f;
        #pragma unroll
        for (int m = 0; m < Fn; m++) {
            float e = ei[n] + ej[m];
            e = e > 0.f ? e : 0.2f * e;
            em[m] = e; mx = fmaxf(mx, e);
        }
        float ss = 0.f;
        #pragma unroll
        for (int m = 0; m < Fn; m++) { em[m] = expf(em[m] - mx); ss += em[m]; }
        float inv = 1.f / ss, acc = 0.f;
        #pragma unroll
        for (int m = 0; m < Fn; m++) acc = fmaf(em[m], hp[m], acc);
        float hn = acc * inv + xs[n * Dn + t];
        gnn[n] = hn > 0.f ? hn : expm1f(hn);
    }

    #pragma unroll
    for (int n = 0; n < Fn; n++) {
        float v = gnn[n];
        #pragma unroll
        for (int o = 16; o; o >>= 1) v += __shfl_xor_sync(0xffffffffu, v, o);
        if (!lane) red[h * Fn + n] = v;
    }
    __syncthreads();

    float wv[Fn];
    {
        float z[Fn];
        #pragma unroll
        for (int n = 0; n < Fn; n++)
            z[n] = (red[0 * Fn + n] + red[1 * Fn + n] + red[2 * Fn + n] + red[3 * Fn + n]) * (1.f / Dn);
        float a[3];
        #pragma unroll
        for (int k = 0; k < 3; k++) {
            float v = se_b1[k];
            #pragma unroll
            for (int n = 0; n < Fn; n++) v = fmaf(z[n], se_w1[n * 3 + k], v);
            a[k] = fmaxf(v, 0.f);
        }
        #pragma unroll
        for (int f = 0; f < Fn; f++) {
            float v = se_b2[f];
            #pragma unroll
            for (int k = 0; k < 3; k++) v = fmaf(a[k], se_w2[k * 6 + f], v);
            wv[f] = 1.f / (1.f + expf(-v));
        }
    }

    __half* ch = g_c + (size_t)b * CINn;
    __half* sb = g_s + (size_t)b * Fn * Dn;
    #pragma unroll
    for (int n = 0; n < Fn; n++) {
        float v = gnn[n];
        ch[n * Dn + t] = __float2half(v);
        sb[n * Dn + t] = __float2half(v * wv[n]);
    }
}

// ---------------- weight prep: transpose + fp16 ------------------------------
__global__ __launch_bounds__(256) void k_wt(
    const float* __restrict__ W, __half* __restrict__ T, int K, int N)
{
    int idx = blockIdx.x * 256 + threadIdx.x;
    if (idx >= K * N) return;
    int k = idx / N, n = idx - k * N;
    T[(size_t)n * K + k] = __float2half(W[idx]);
}
// bi_W[f][d][e] -> [f][n=e][k=d], fp16
__global__ __launch_bounds__(256) void k_wbi(const float* __restrict__ W)
{
    int idx = blockIdx.x * 256 + threadIdx.x;
    if (idx >= 5 * 128 * 128) return;
    int f = idx >> 14, rem = idx & 16383;
    int d = rem >> 7, e = rem & 127;
    g_wb[(f << 14) + e * 128 + d] = __float2half(W[idx]);
}

// ---------------- fp16 GEMM via mma.sync + fused epilogue --------------------
// D[M,N] = A[M,K] @ B[N,K]^T, both fp16. z-batched via az/bz (elems).
// modes: 1 = bias+bn+gelu -> fp16; 2 = bias+bn+gelu -> fp32;
//        3 = bilinear-pairs: z = field i, D = vid[b,i,:]; write
//            c[b, pair(i,j), :] = vid * s[b,j,:] for j > i (fused k_pairs).
#define BM 128
#define BN 128
#define BK 32
#define ROWB 80u
#define OFF_A  0u
#define OFF_B  10240u
#define STAGEB 20480u
#define NSTAGE 4
#define SMEM_MMA (NSTAGE * STAGEB)

__global__ __launch_bounds__(256, 1) void k_mma(
    const __half* __restrict__ A, const __half* __restrict__ B,
    int K, int lda, long az, long bz,
    float* __restrict__ outf, __half* __restrict__ oh, int ldc,
    const float* __restrict__ bias, const float* __restrict__ bng,
    const float* __restrict__ bnb, int mode)
{
    extern __shared__ char smem[];
    const uint32_t sbase = smem_u32(smem);
    const int tid = threadIdx.x;
    const int lane = tid & 31, wid = tid >> 5;
    const int wm = wid >> 2, wn = wid & 3;
    const int bm = blockIdx.y * BM, bn = blockIdx.x * BN;
    const int z = blockIdx.z;
    A += (size_t)z * az;
    B += (size_t)z * bz;

    float acc[4][4][4];
    #pragma unroll
    for (int mi = 0; mi < 4; mi++)
        #pragma unroll
        for (int ni = 0; ni < 4; ni++)
            #pragma unroll
            for (int q = 0; q < 4; q++) acc[mi][ni][q] = 0.f;

    const uint32_t a_base = (uint32_t)(wm * 64 + (lane & 15)) * ROWB + (uint32_t)((lane >> 4) * 16);
    const uint32_t b_base = (uint32_t)(wn * 32 + (lane & 7) + ((lane >> 4) << 3)) * ROWB
                          + (uint32_t)(((lane >> 3) & 1) * 16);

    const int nIter = K / BK;

    auto load_stage = [&](int buf, int k0) {
        uint32_t base = sbase + (uint32_t)buf * STAGEB;
        #pragma unroll
        for (int half = 0; half < 2; half++) {
            int e = tid + half * 256;
            int r = e >> 2, c = e & 3;
            uint32_t off = (uint32_t)r * ROWB + (uint32_t)c * 16;
            cp16(base + OFF_A + off, A + (size_t)(bm + r) * lda + k0 + c * 8);
            cp16(base + OFF_B + off, B + (size_t)(bn + r) * K   + k0 + c * 8);
        }
    };

    load_stage(0, 0);
    cp_commit();
    load_stage(1, BK);
    cp_commit();
    load_stage(2, 2 * BK);
    cp_commit();

    for (int it = 0; it < nIter; it++) {
        if (it + 3 < nIter) {
            load_stage((it + 3) & 3, (it + 3) * BK);
            cp_commit();
            cp_wait<3>();
        } else if (it + 2 < nIter) {
            cp_wait<2>();
        } else if (it + 1 < nIter) {
            cp_wait<1>();
        } else {
            cp_wait<0>();
        }
        __syncthreads();

        uint32_t base = sbase + (uint32_t)(it & 3) * STAGEB;
        #pragma unroll
        for (int ks = 0; ks < 2; ks++) {
            uint32_t koff = (uint32_t)ks * 32;
            uint32_t a[4][4], bb[2][4];
            #pragma unroll
            for (int mi = 0; mi < 4; mi++)
                ldsm4(a[mi], base + OFF_A + a_base + (uint32_t)mi * 16 * ROWB + koff);
            #pragma unroll
            for (int nq = 0; nq < 2; nq++)
                ldsm4(bb[nq], base + OFF_B + b_base + (uint32_t)nq * 16 * ROWB + koff);
            #pragma unroll
            for (int mi = 0; mi < 4; mi++)
                #pragma unroll
                for (int ni = 0; ni < 4; ni++)
                    mma_fp16(acc[mi][ni], a[mi], &bb[ni >> 1][(ni & 1) * 2]);
        }
        __syncthreads();
    }

    const float bnscale = 0.999995000037499688f;  // 1/sqrt(1+1e-5)
    const int poff = z * (11 - z) / 2;            // pair-row offset for mode 3
    #pragma unroll
    for (int ni = 0; ni < 4; ni++) {
        int col = bn + wn * 32 + ni * 8 + (lane & 3) * 2;
        float bi0 = 0.f, bi1 = 0.f, g0 = 1.f, g1 = 1.f, bb0 = 0.f, bb1 = 0.f;
        if (mode != 3) {
            bi0 = bias[col];             bi1 = bias[col + 1];
            g0 = bng[col] * bnscale;     g1 = bng[col + 1] * bnscale;
            bb0 = bnb[col];              bb1 = bnb[col + 1];
        }
        #pragma unroll
        for (int mi = 0; mi < 4; mi++) {
            int r0 = bm + wm * 64 + mi * 16 + (lane >> 2);
            #pragma unroll
            for (int half = 0; half < 2; half++) {
                int row = r0 + half * 8;
                float v0 = acc[mi][ni][half * 2 + 0];
                float v1 = acc[mi][ni][half * 2 + 1];
                if (mode == 3) {
                    // fused pairs: c[row, pair(z,j), col] = vid * s[row, j, col]
                    const __half* sb = g_s + (size_t)row * (Fn * Dn);
                    __half* cp = g_c + (size_t)row * CINn + Fn * Dn;
                    for (int j = z + 1; j < Fn; j++) {
                        int p = poff + j - z - 1;
                        float s0 = __half2float(sb[j * Dn + col]);
                        float s1 = __half2float(sb[j * Dn + col + 1]);
                        cp[p * Dn + col]     = __float2half(v0 * s0);
                        cp[p * Dn + col + 1] = __float2half(v1 * s1);
                    }
                    continue;
                }
                v0 = (v0 + bi0) * g0 + bb0;
                v1 = (v1 + bi1) * g1 + bb1;
                v0 = 0.5f * v0 * (1.f + erff(v0 * 0.70710678118654752f));
                v1 = 0.5f * v1 * (1.f + erff(v1 * 0.70710678118654752f));
                if (mode == 2) {
                    outf[(size_t)row * ldc + col]     = v0;
                    outf[(size_t)row * ldc + col + 1] = v1;
                } else {
                    oh[(size_t)row * ldc + col]     = __float2half(v0);
                    oh[(size_t)row * ldc + col + 1] = __float2half(v1);
                }
            }
        }
    }
}

// ---------------- K5: final dot + sigmoid ------------------------------------
__global__ __launch_bounds__(256) void k_final(
    const float* __restrict__ w3, const float* __restrict__ b3,
    float* __restrict__ out)
{
    int warp = threadIdx.x >> 5, lane = threadIdx.x & 31;
    int b = blockIdx.x * 8 + warp;
    const float* hh = g_h2 + (size_t)b * H2N;
    float acc = 0.f;
    #pragma unroll
    for (int i = 0; i < 8; i++) acc = fmaf(hh[lane + i * 32], w3[lane + i * 32], acc);
    #pragma unroll
    for (int o = 16; o; o >>= 1) acc += __shfl_xor_sync(0xffffffffu, acc, o);
    if (!lane) out[b] = 1.f / (1.f + expf(-(acc + b3[0])));
}

// ---------------- launch -----------------------------------------------------
extern "C" void kernel_launch(void* const* d_in, const int* in_sizes, int n_in,
                              void* d_out, int out_size)
{
    const int*   item_id  = (const int*)  d_in[0];
    const float* item_mm  = (const float*)d_in[1];
    const int*   likes    = (const int*)  d_in[2];
    const int*   views    = (const int*)  d_in[3];
    const int*   item_seq = (const int*)  d_in[4];
    const float* item_emb = (const float*)d_in[5];
    const float* cate_emb = (const float*)d_in[6];
    const float* mm_w     = (const float*)d_in[7];
    const float* mm_b     = (const float*)d_in[8];
    const float* ln_g     = (const float*)d_in[9];
    const float* ln_b     = (const float*)d_in[10];
    const float* gnn_W    = (const float*)d_in[11];
    const float* gnn_a    = (const float*)d_in[12];
    const float* se_w1    = (const float*)d_in[13];
    const float* se_b1    = (const float*)d_in[14];
    const float* se_w2    = (const float*)d_in[15];
    const float* se_b2    = (const float*)d_in[16];
    const float* bi_W     = (const float*)d_in[17];
    const float* w1       = (const float*)d_in[18];
    const float* b1       = (const float*)d_in[19];
    const float* bn1g     = (const float*)d_in[20];
    const float* bn1b     = (const float*)d_in[21];
    const float* w2       = (const float*)d_in[22];
    const float* b2       = (const float*)d_in[23];
    const float* bn2g     = (const float*)d_in[24];
    const float* bn2b     = (const float*)d_in[25];
    const float* w3       = (const float*)d_in[26];
    const float* b3       = (const float*)d_in[27];
    float* out = (float*)d_out;

    float *ph2;
    __half *ps, *pc, *ph1, *pw1, *pw2, *pwb;
    cudaGetSymbolAddress((void**)&ps,   g_s);
    cudaGetSymbolAddress((void**)&ph2,  g_h2);
    cudaGetSymbolAddress((void**)&pc,   g_c);
    cudaGetSymbolAddress((void**)&ph1,  g_h1);
    cudaGetSymbolAddress((void**)&pw1,  g_w1t);
    cudaGetSymbolAddress((void**)&pw2,  g_w2t);
    cudaGetSymbolAddress((void**)&pwb,  g_wb);

    cudaFuncSetAttribute(k_mma, cudaFuncAttributeMaxDynamicSharedMemorySize, SMEM_MMA);

    // weight prep (fp16 transpose)
    k_wt<<<(CINn * H1N + 255) / 256, 256>>>(w1, pw1, CINn, H1N);
    k_wt<<<(H1N * H2N + 255) / 256, 256>>>(w2, pw2, H1N, H2N);
    k_wbi<<<(5 * 128 * 128 + 255) / 256, 256>>>(bi_W);

    k_features<<<Bn, 128>>>(item_id, item_mm, likes, views, item_seq,
                            item_emb, cate_emb, mm_w, mm_b, ln_g, ln_b);
    k_gnn<<<Bn, 128>>>(gnn_W, gnn_a, se_w1, se_b1, se_w2, se_b2);

    // bilinear + fused pairs: z = field i; writes c[:, 768:] directly
    {
        dim3 grid(1, Bn / BM, 5);
        k_mma<<<grid, 256, SMEM_MMA>>>(ps, pwb, Dn, Fn * Dn, Dn, (long)Dn * Dn,
                                       nullptr, nullptr, 0,
                                       nullptr, nullptr, nullptr, 3);
    }

    // layer 1: c @ w1 (+bias,bn,gelu) -> h1 (fp16)
    {
        dim3 grid(H1N / BN, Bn / BM, 1);
        k_mma<<<grid, 256, SMEM_MMA>>>(pc, pw1, CINn, CINn, 0, 0,
                                       nullptr, ph1, H1N, b1, bn1g, bn1b, 1);
    }
    // layer 2: h1 @ w2 (+bias,bn,gelu) -> h2 (fp32)
    {
        dim3 grid(H2N / BN, Bn / BM, 1);
        k_mma<<<grid, 256, SMEM_MMA>>>(ph1, pw2, H1N, H1N, 0, 0,
                                       ph2, nullptr, H2N, b2, bn2g, bn2b, 2);
    }
    k_final<<<Bn / 8, 256>>>(w3, b3, out);
}

// round 10
// speedup vs baseline: 2.2817x; 1.0310x over previous
#include <cuda_runtime.h>
#include <cuda_fp16.h>
#include <math.h>
#include <stdint.h>

#define Bn 16384
#define Ln 50
#define Dn 128
#define Fn 6
#define CINn 2688
#define H1N 512
#define H2N 256

// ---------------- scratch (static device globals) ---------------------------
__device__ __align__(16) __half g_s  [Bn * Fn * Dn];   // fp16 SE-scaled feats
__device__ __align__(16) __half g_c  [Bn * CINn];      // fp16 activations
__device__ __align__(16) __half g_h1 [Bn * H1N];
__device__ __align__(16) float g_h2 [Bn * H2N];
__device__ __align__(16) __half g_w1t[H1N * CINn];     // fp16 weights (transposed)
__device__ __align__(16) __half g_w2t[H2N * H1N];
__device__ __align__(16) __half g_wb [5 * Dn * Dn];    // bi_W as [f][e][d]

// ---------------- PTX helpers (sm_80-level only) -----------------------------
__device__ __forceinline__ uint32_t smem_u32(const void* p) {
    uint32_t a;
    asm("{ .reg .u64 t; cvta.to.shared.u64 t, %1; cvt.u32.u64 %0, t; }" : "=r"(a) : "l"(p));
    return a;
}
__device__ __forceinline__ void cp16(uint32_t dst, const void* src) {
    asm volatile("cp.async.cg.shared.global [%0], [%1], 16;" :: "r"(dst), "l"(src));
}
__device__ __forceinline__ void cp_commit() {
    asm volatile("cp.async.commit_group;" ::: "memory");
}
template <int N>
__device__ __forceinline__ void cp_wait() {
    asm volatile("cp.async.wait_group %0;" :: "n"(N) : "memory");
}
__device__ __forceinline__ void ldsm4(uint32_t* r, uint32_t addr) {
    asm volatile("ldmatrix.sync.aligned.m8n8.x4.shared.b16 {%0,%1,%2,%3}, [%4];"
                 : "=r"(r[0]), "=r"(r[1]), "=r"(r[2]), "=r"(r[3]) : "r"(addr));
}
__device__ __forceinline__ void mma_fp16(float* d, const uint32_t* a, const uint32_t* b) {
    asm volatile(
        "mma.sync.aligned.m16n8k16.row.col.f32.f16.f16.f32 "
        "{%0,%1,%2,%3}, {%4,%5,%6,%7}, {%8,%9}, {%0,%1,%2,%3};"
        : "+f"(d[0]), "+f"(d[1]), "+f"(d[2]), "+f"(d[3])
        : "r"(a[0]), "r"(a[1]), "r"(a[2]), "r"(a[3]), "r"(b[0]), "r"(b[1]));
}

// ---------------- K1: fused features + GAT + SE ------------------------------
// features -> xs (smem), then GNN/SE -> c[:, :768] (fp16) and s (fp16).
__global__ __launch_bounds__(128) void k_feat_gnn(
    const int* __restrict__ item_id, const float* __restrict__ item_mm,
    const int* __restrict__ likes, const int* __restrict__ views,
    const int* __restrict__ item_seq, const float* __restrict__ item_emb,
    const float* __restrict__ cate_emb, const float* __restrict__ mm_w,
    const float* __restrict__ mm_b, const float* __restrict__ ln_g,
    const float* __restrict__ ln_b,
    const float* __restrict__ gnn_W, const float* __restrict__ gnn_a,
    const float* __restrict__ se_w1, const float* __restrict__ se_b1,
    const float* __restrict__ se_w2, const float* __restrict__ se_b2)
{
    int b = blockIdx.x, t = threadIdx.x;
    int lane = t & 31, w = t >> 5;
    int h = w;
    __shared__ float xs[Fn * Dn];
    __shared__ float sm[Dn];
    __shared__ float red[8];
    __shared__ float red2[4 * Fn];
    __shared__ int sseq[Ln];

    // ---- features phase ----
    sm[t] = item_mm[b * Dn + t];
    if (t < Ln) sseq[t] = item_seq[b * Ln + t];
    __syncthreads();

    float y = mm_b[t];
    {
        const float* Wc = mm_w + t;
        #pragma unroll
        for (int c = 0; c < 4; c++) {
            float wv[32];
            #pragma unroll
            for (int q = 0; q < 32; q++) wv[q] = Wc[(c * 32 + q) * Dn];
            const float4* xv = reinterpret_cast<const float4*>(&sm[c * 32]);
            #pragma unroll
            for (int q8 = 0; q8 < 8; q8++) {
                float4 v = xv[q8];
                y = fmaf(v.x, wv[q8 * 4 + 0], y);
                y = fmaf(v.y, wv[q8 * 4 + 1], y);
                y = fmaf(v.z, wv[q8 * 4 + 2], y);
                y = fmaf(v.w, wv[q8 * 4 + 3], y);
            }
        }
    }

    float s1 = y, s2 = y * y;
    #pragma unroll
    for (int o = 16; o; o >>= 1) {
        s1 += __shfl_xor_sync(0xffffffffu, s1, o);
        s2 += __shfl_xor_sync(0xffffffffu, s2, o);
    }
    if (!lane) { red[w] = s1; red[4 + w] = s2; }
    __syncthreads();
    float mu = (red[0] + red[1] + red[2] + red[3]) * (1.f / Dn);
    float m2 = (red[4] + red[5] + red[6] + red[7]) * (1.f / Dn);
    float var = m2 - mu * mu;
    float yn = (y - mu) * rsqrtf(var + 1e-5f) * ln_g[t] + ln_b[t];
    float img = 0.5f * yn * (1.f + erff(yn * 0.70710678118654752f));

    // branch-free masked mean: item_emb[0] == 0 by construction
    float hs = 0.f;
    int cnt = 0;
    #pragma unroll 10
    for (int l = 0; l < Ln; l++) {
        int id = sseq[l];
        hs += item_emb[(size_t)id * Dn + t];
        cnt += (id != 0);
    }
    float hist = hs / fmaxf((float)cnt, 1.f);

    xs[0 * Dn + t] = 0.f;
    xs[1 * Dn + t] = cate_emb[likes[b] * Dn + t];
    xs[2 * Dn + t] = cate_emb[views[b] * Dn + t];
    xs[3 * Dn + t] = item_emb[(size_t)item_id[b] * Dn + t];
    xs[4 * Dn + t] = img;
    xs[5 * Dn + t] = hist;
    __syncthreads();

    // ---- GAT phase: hp[n] = sum_i xs[n][i] * W[h][i][lane] ----
    float hp[Fn];
    #pragma unroll
    for (int n = 0; n < Fn; n++) hp[n] = 0.f;
    const float* Wh = gnn_W + h * (Dn * 32) + lane;
    #pragma unroll
    for (int c = 0; c < 4; c++) {
        float wv[32];
        #pragma unroll
        for (int q = 0; q < 32; q++) wv[q] = Wh[(c * 32 + q) * 32];
        #pragma unroll
        for (int n = 0; n < Fn; n++) {
            const float4* xv = reinterpret_cast<const float4*>(&xs[n * Dn + c * 32]);
            float a = hp[n];
            #pragma unroll
            for (int q8 = 0; q8 < 8; q8++) {
                float4 v = xv[q8];
                a = fmaf(v.x, wv[q8 * 4 + 0], a);
                a = fmaf(v.y, wv[q8 * 4 + 1], a);
                a = fmaf(v.z, wv[q8 * 4 + 2], a);
                a = fmaf(v.w, wv[q8 * 4 + 3], a);
            }
            hp[n] = a;
        }
    }

    float a1 = gnn_a[h * 64 + lane];
    float a2 = gnn_a[h * 64 + 32 + lane];
    float ei[Fn], ej[Fn];
    #pragma unroll
    for (int n = 0; n < Fn; n++) {
        float v1 = hp[n] * a1, v2 = hp[n] * a2;
        #pragma unroll
        for (int o = 16; o; o >>= 1) {
            v1 += __shfl_xor_sync(0xffffffffu, v1, o);
            v2 += __shfl_xor_sync(0xffffffffu, v2, o);
        }
        ei[n] = v1; ej[n] = v2;
    }

    float gnn[Fn];
    #pragma unroll
    for (int n = 0; n < Fn; n++) {
        float em[Fn], mx = -1e30f;
        #pragma unroll
        for (int m = 0; m < Fn; m++) {
            float e = ei[n] + ej[m];
            e = e > 0.f ? e : 0.2f * e;
            em[m] = e; mx = fmaxf(mx, e);
        }
        float ss = 0.f;
        #pragma unroll
        for (int m = 0; m < Fn; m++) { em[m] = expf(em[m] - mx); ss += em[m]; }
        float inv = 1.f / ss, acc = 0.f;
        #pragma unroll
        for (int m = 0; m < Fn; m++) acc = fmaf(em[m], hp[m], acc);
        float hn = acc * inv + xs[n * Dn + t];
        gnn[n] = hn > 0.f ? hn : expm1f(hn);
    }

    #pragma unroll
    for (int n = 0; n < Fn; n++) {
        float v = gnn[n];
        #pragma unroll
        for (int o = 16; o; o >>= 1) v += __shfl_xor_sync(0xffffffffu, v, o);
        if (!lane) red2[h * Fn + n] = v;
    }
    __syncthreads();

    float wv[Fn];
    {
        float z[Fn];
        #pragma unroll
        for (int n = 0; n < Fn; n++)
            z[n] = (red2[0 * Fn + n] + red2[1 * Fn + n] + red2[2 * Fn + n] + red2[3 * Fn + n]) * (1.f / Dn);
        float a[3];
        #pragma unroll
        for (int k = 0; k < 3; k++) {
            float v = se_b1[k];
            #pragma unroll
            for (int n = 0; n < Fn; n++) v = fmaf(z[n], se_w1[n * 3 + k], v);
            a[k] = fmaxf(v, 0.f);
        }
        #pragma unroll
        for (int f = 0; f < Fn; f++) {
            float v = se_b2[f];
            #pragma unroll
            for (int k = 0; k < 3; k++) v = fmaf(a[k], se_w2[k * 6 + f], v);
            wv[f] = 1.f / (1.f + expf(-v));
        }
    }

    __half* ch = g_c + (size_t)b * CINn;
    __half* sb = g_s + (size_t)b * Fn * Dn;
    #pragma unroll
    for (int n = 0; n < Fn; n++) {
        float v = gnn[n];
        ch[n * Dn + t] = __float2half(v);
        sb[n * Dn + t] = __float2half(v * wv[n]);
    }
}

// ---------------- weight prep: transpose + fp16 ------------------------------
__global__ __launch_bounds__(256) void k_wt(
    const float* __restrict__ W, __half* __restrict__ T, int K, int N)
{
    int idx = blockIdx.x * 256 + threadIdx.x;
    if (idx >= K * N) return;
    int k = idx / N, n = idx - k * N;
    T[(size_t)n * K + k] = __float2half(W[idx]);
}
// bi_W[f][d][e] -> [f][n=e][k=d], fp16
__global__ __launch_bounds__(256) void k_wbi(const float* __restrict__ W)
{
    int idx = blockIdx.x * 256 + threadIdx.x;
    if (idx >= 5 * 128 * 128) return;
    int f = idx >> 14, rem = idx & 16383;
    int d = rem >> 7, e = rem & 127;
    g_wb[(f << 14) + e * 128 + d] = __float2half(W[idx]);
}

// ---------------- shared GEMM constants --------------------------------------
#define BK 32
#define ROWB 80u

// ---------------- k_mma128: BN=128 (bilinear + fused pairs) ------------------
#define BM 128
#define BN 128
#define OFF_A  0u
#define OFF_B  10240u
#define STAGEB 20480u
#define NSTAGE 4
#define SMEM_MMA (NSTAGE * STAGEB)

__global__ __launch_bounds__(256, 1) void k_mma128(
    const __half* __restrict__ A, const __half* __restrict__ B,
    int K, int lda, long az, long bz)
{
    extern __shared__ char smem[];
    const uint32_t sbase = smem_u32(smem);
    const int tid = threadIdx.x;
    const int lane = tid & 31, wid = tid >> 5;
    const int wm = wid >> 2, wn = wid & 3;
    const int bm = blockIdx.y * BM, bn = blockIdx.x * BN;
    const int z = blockIdx.z;
    A += (size_t)z * az;
    B += (size_t)z * bz;

    float acc[4][4][4];
    #pragma unroll
    for (int mi = 0; mi < 4; mi++)
        #pragma unroll
        for (int ni = 0; ni < 4; ni++)
            #pragma unroll
            for (int q = 0; q < 4; q++) acc[mi][ni][q] = 0.f;

    const uint32_t a_base = (uint32_t)(wm * 64 + (lane & 15)) * ROWB + (uint32_t)((lane >> 4) * 16);
    const uint32_t b_base = (uint32_t)(wn * 32 + (lane & 7) + ((lane >> 4) << 3)) * ROWB
                          + (uint32_t)(((lane >> 3) & 1) * 16);

    const int nIter = K / BK;

    auto load_stage = [&](int buf, int k0) {
        uint32_t base = sbase + (uint32_t)buf * STAGEB;
        #pragma unroll
        for (int half = 0; half < 2; half++) {
            int e = tid + half * 256;
            int r = e >> 2, c = e & 3;
            uint32_t off = (uint32_t)r * ROWB + (uint32_t)c * 16;
            cp16(base + OFF_A + off, A + (size_t)(bm + r) * lda + k0 + c * 8);
            cp16(base + OFF_B + off, B + (size_t)(bn + r) * K   + k0 + c * 8);
        }
    };

    load_stage(0, 0);
    cp_commit();
    load_stage(1, BK);
    cp_commit();
    load_stage(2, 2 * BK);
    cp_commit();

    for (int it = 0; it < nIter; it++) {
        if (it + 3 < nIter) {
            load_stage((it + 3) & 3, (it + 3) * BK);
            cp_commit();
            cp_wait<3>();
        } else if (it + 2 < nIter) {
            cp_wait<2>();
        } else if (it + 1 < nIter) {
            cp_wait<1>();
        } else {
            cp_wait<0>();
        }
        __syncthreads();

        uint32_t base = sbase + (uint32_t)(it & 3) * STAGEB;
        #pragma unroll
        for (int ks = 0; ks < 2; ks++) {
            uint32_t koff = (uint32_t)ks * 32;
            uint32_t a[4][4], bb[2][4];
            #pragma unroll
            for (int mi = 0; mi < 4; mi++)
                ldsm4(a[mi], base + OFF_A + a_base + (uint32_t)mi * 16 * ROWB + koff);
            #pragma unroll
            for (int nq = 0; nq < 2; nq++)
                ldsm4(bb[nq], base + OFF_B + b_base + (uint32_t)nq * 16 * ROWB + koff);
            #pragma unroll
            for (int mi = 0; mi < 4; mi++)
                #pragma unroll
                for (int ni = 0; ni < 4; ni++)
                    mma_fp16(acc[mi][ni], a[mi], &bb[ni >> 1][(ni & 1) * 2]);
        }
        __syncthreads();
    }

    // fused pairs epilogue: c[row, pair(z,j), col] = vid * s[row, j, col]
    const int poff = z * (11 - z) / 2;
    #pragma unroll
    for (int ni = 0; ni < 4; ni++) {
        int col = bn + wn * 32 + ni * 8 + (lane & 3) * 2;
        #pragma unroll
        for (int mi = 0; mi < 4; mi++) {
            int r0 = bm + wm * 64 + mi * 16 + (lane >> 2);
            #pragma unroll
            for (int half = 0; half < 2; half++) {
                int row = r0 + half * 8;
                float v0 = acc[mi][ni][half * 2 + 0];
                float v1 = acc[mi][ni][half * 2 + 1];
                const __half* sb = g_s + (size_t)row * (Fn * Dn);
                __half* cp = g_c + (size_t)row * CINn + Fn * Dn;
                for (int j = z + 1; j < Fn; j++) {
                    int p = poff + j - z - 1;
                    float s0 = __half2float(sb[j * Dn + col]);
                    float s1 = __half2float(sb[j * Dn + col + 1]);
                    cp[p * Dn + col]     = __float2half(v0 * s0);
                    cp[p * Dn + col + 1] = __float2half(v1 * s1);
                }
            }
        }
    }
}

// ---------------- k_mma256: BN=256, warp tile 64x64 (MLP layers) -------------
#define BM2 128
#define BN2 256
#define OFF_A2  0u
#define OFF_B2  10240u
#define STAGEB2 30720u
#define NSTAGE2 4
#define SMEM_MMA2 (NSTAGE2 * STAGEB2)

__global__ __launch_bounds__(256, 1) void k_mma256(
    const __half* __restrict__ A, const __half* __restrict__ B,
    int K,
    float* __restrict__ outf, __half* __restrict__ oh, int ldc,
    const float* __restrict__ bias, const float* __restrict__ bng,
    const float* __restrict__ bnb, int mode)
{
    extern __shared__ char smem[];
    const uint32_t sbase = smem_u32(smem);
    const int tid = threadIdx.x;
    const int lane = tid & 31, wid = tid >> 5;
    const int wm = wid >> 2, wn = wid & 3;          // 2(M) x 4(N), warp 64x64
    const int bm = blockIdx.y * BM2, bn = blockIdx.x * BN2;

    float acc[4][8][4];
    #pragma unroll
    for (int mi = 0; mi < 4; mi++)
        #pragma unroll
        for (int ni = 0; ni < 8; ni++)
            #pragma unroll
            for (int q = 0; q < 4; q++) acc[mi][ni][q] = 0.f;

    const uint32_t a_base = (uint32_t)(wm * 64 + (lane & 15)) * ROWB + (uint32_t)((lane >> 4) * 16);
    const uint32_t b_base = (uint32_t)(wn * 64 + (lane & 7) + ((lane >> 4) << 3)) * ROWB
                          + (uint32_t)(((lane >> 3) & 1) * 16);

    const int nIter = K / BK;

    auto load_stage = [&](int buf, int k0) {
        uint32_t base = sbase + (uint32_t)buf * STAGEB2;
        // A: 128 rows x 4 chunks = 512 cp16
        #pragma unroll
        for (int half = 0; half < 2; half++) {
            int e = tid + half * 256;
            int r = e >> 2, c = e & 3;
            uint32_t off = (uint32_t)r * ROWB + (uint32_t)c * 16;
            cp16(base + OFF_A2 + off, A + (size_t)(bm + r) * K + k0 + c * 8);
        }
        // B: 256 rows x 4 chunks = 1024 cp16
        #pragma unroll
        for (int half = 0; half < 4; half++) {
            int e = tid + half * 256;
            int r = e >> 2, c = e & 3;
            uint32_t off = (uint32_t)r * ROWB + (uint32_t)c * 16;
            cp16(base + OFF_B2 + off, B + (size_t)(bn + r) * K + k0 + c * 8);
        }
    };

    load_stage(0, 0);
    cp_commit();
    load_stage(1, BK);
    cp_commit();
    load_stage(2, 2 * BK);
    cp_commit();

    for (int it = 0; it < nIter; it++) {
        if (it + 3 < nIter) {
            load_stage((it + 3) & 3, (it + 3) * BK);
            cp_commit();
            cp_wait<3>();
        } else if (it + 2 < nIter) {
            cp_wait<2>();
        } else if (it + 1 < nIter) {
            cp_wait<1>();
        } else {
            cp_wait<0>();
        }
        __syncthreads();

        uint32_t base = sbase + (uint32_t)(it & 3) * STAGEB2;
        #pragma unroll
        for (int ks = 0; ks < 2; ks++) {
            uint32_t koff = (uint32_t)ks * 32;
            uint32_t a[4][4], bb[4][4];
            #pragma unroll
            for (int mi = 0; mi < 4; mi++)
                ldsm4(a[mi], base + OFF_A2 + a_base + (uint32_t)mi * 16 * ROWB + koff);
            #pragma unroll
            for (int nq = 0; nq < 4; nq++)
                ldsm4(bb[nq], base + OFF_B2 + b_base + (uint32_t)nq * 16 * ROWB + koff);
            #pragma unroll
            for (int mi = 0; mi < 4; mi++)
                #pragma unroll
                for (int ni = 0; ni < 8; ni++)
                    mma_fp16(acc[mi][ni], a[mi], &bb[ni >> 1][(ni & 1) * 2]);
        }
        __syncthreads();
    }

    const float bnscale = 0.999995000037499688f;  // 1/sqrt(1+1e-5)
    #pragma unroll
    for (int ni = 0; ni < 8; ni++) {
        int col = bn + wn * 64 + ni * 8 + (lane & 3) * 2;
        float bi0 = bias[col],         bi1 = bias[col + 1];
        float g0 = bng[col] * bnscale, g1 = bng[col + 1] * bnscale;
        float bb0 = bnb[col],          bb1 = bnb[col + 1];
        #pragma unroll
        for (int mi = 0; mi < 4; mi++) {
            int r0 = bm + wm * 64 + mi * 16 + (lane >> 2);
            #pragma unroll
            for (int half = 0; half < 2; half++) {
                int row = r0 + half * 8;
                float v0 = acc[mi][ni][half * 2 + 0];
                float v1 = acc[mi][ni][half * 2 + 1];
                v0 = (v0 + bi0) * g0 + bb0;
                v1 = (v1 + bi1) * g1 + bb1;
                v0 = 0.5f * v0 * (1.f + erff(v0 * 0.70710678118654752f));
                v1 = 0.5f * v1 * (1.f + erff(v1 * 0.70710678118654752f));
                if (mode == 2) {
                    outf[(size_t)row * ldc + col]     = v0;
                    outf[(size_t)row * ldc + col + 1] = v1;
                } else {
                    oh[(size_t)row * ldc + col]     = __float2half(v0);
                    oh[(size_t)row * ldc + col + 1] = __float2half(v1);
                }
            }
        }
    }
}

// ---------------- K5: final dot + sigmoid ------------------------------------
__global__ __launch_bounds__(256) void k_final(
    const float* __restrict__ w3, const float* __restrict__ b3,
    float* __restrict__ out)
{
    int warp = threadIdx.x >> 5, lane = threadIdx.x & 31;
    int b = blockIdx.x * 8 + warp;
    const float* hh = g_h2 + (size_t)b * H2N;
    float acc = 0.f;
    #pragma unroll
    for (int i = 0; i < 8; i++) acc = fmaf(hh[lane + i * 32], w3[lane + i * 32], acc);
    #pragma unroll
    for (int o = 16; o; o >>= 1) acc += __shfl_xor_sync(0xffffffffu, acc, o);
    if (!lane) out[b] = 1.f / (1.f + expf(-(acc + b3[0])));
}

// ---------------- launch -----------------------------------------------------
extern "C" void kernel_launch(void* const* d_in, const int* in_sizes, int n_in,
                              void* d_out, int out_size)
{
    const int*   item_id  = (const int*)  d_in[0];
    const float* item_mm  = (const float*)d_in[1];
    const int*   likes    = (const int*)  d_in[2];
    const int*   views    = (const int*)  d_in[3];
    const int*   item_seq = (const int*)  d_in[4];
    const float* item_emb = (const float*)d_in[5];
    const float* cate_emb = (const float*)d_in[6];
    const float* mm_w     = (const float*)d_in[7];
    const float* mm_b     = (const float*)d_in[8];
    const float* ln_g     = (const float*)d_in[9];
    const float* ln_b     = (const float*)d_in[10];
    const float* gnn_W    = (const float*)d_in[11];
    const float* gnn_a    = (const float*)d_in[12];
    const float* se_w1    = (const float*)d_in[13];
    const float* se_b1    = (const float*)d_in[14];
    const float* se_w2    = (const float*)d_in[15];
    const float* se_b2    = (const float*)d_in[16];
    const float* bi_W     = (const float*)d_in[17];
    const float* w1       = (const float*)d_in[18];
    const float* b1       = (const float*)d_in[19];
    const float* bn1g     = (const float*)d_in[20];
    const float* bn1b     = (const float*)d_in[21];
    const float* w2       = (const float*)d_in[22];
    const float* b2       = (const float*)d_in[23];
    const float* bn2g     = (const float*)d_in[24];
    const float* bn2b     = (const float*)d_in[25];
    const float* w3       = (const float*)d_in[26];
    const float* b3       = (const float*)d_in[27];
    float* out = (float*)d_out;

    float *ph2;
    __half *ps, *pc, *ph1, *pw1, *pw2, *pwb;
    cudaGetSymbolAddress((void**)&ps,   g_s);
    cudaGetSymbolAddress((void**)&ph2,  g_h2);
    cudaGetSymbolAddress((void**)&pc,   g_c);
    cudaGetSymbolAddress((void**)&ph1,  g_h1);
    cudaGetSymbolAddress((void**)&pw1,  g_w1t);
    cudaGetSymbolAddress((void**)&pw2,  g_w2t);
    cudaGetSymbolAddress((void**)&pwb,  g_wb);

    cudaFuncSetAttribute(k_mma128, cudaFuncAttributeMaxDynamicSharedMemorySize, SMEM_MMA);
    cudaFuncSetAttribute(k_mma256, cudaFuncAttributeMaxDynamicSharedMemorySize, SMEM_MMA2);

    // weight prep (fp16 transpose)
    k_wt<<<(CINn * H1N + 255) / 256, 256>>>(w1, pw1, CINn, H1N);
    k_wt<<<(H1N * H2N + 255) / 256, 256>>>(w2, pw2, H1N, H2N);
    k_wbi<<<(5 * 128 * 128 + 255) / 256, 256>>>(bi_W);

    // fused features + GNN + SE
    k_feat_gnn<<<Bn, 128>>>(item_id, item_mm, likes, views, item_seq,
                            item_emb, cate_emb, mm_w, mm_b, ln_g, ln_b,
                            gnn_W, gnn_a, se_w1, se_b1, se_w2, se_b2);

    // bilinear + fused pairs: z = field i; writes c[:, 768:] directly
    {
        dim3 grid(1, Bn / BM, 5);
        k_mma128<<<grid, 256, SMEM_MMA>>>(ps, pwb, Dn, Fn * Dn, Dn, (long)Dn * Dn);
    }

    // layer 1: c @ w1 (+bias,bn,gelu) -> h1 (fp16)
    {
        dim3 grid(H1N / BN2, Bn / BM2, 1);
        k_mma256<<<grid, 256, SMEM_MMA2>>>(pc, pw1, CINn,
                                           nullptr, ph1, H1N, b1, bn1g, bn1b, 1);
    }
    // layer 2: h1 @ w2 (+bias,bn,gelu) -> h2 (fp32)
    {
        dim3 grid(H2N / BN2, Bn / BM2, 1);
        k_mma256<<<grid, 256, SMEM_MMA2>>>(ph1, pw2, H1N,
                                           ph2, nullptr, H2N, b2, bn2g, bn2b, 2);
    }
    k_final<<<Bn / 8, 256>>>(w3, b3, out);
}